// round 6
// baseline (speedup 1.0000x reference)
#include <cuda_runtime.h>
#include <math.h>
#include <complex>

// ---------------- problem constants ----------------
#define TT    16384          // time steps (output rows)
#define BB    512            // batch columns
#define TPAD  16388          // TT + K - 1 (K = 5)
#define LBLK  128            // IIR parallel block length
#define NBLK  128            // number of IIR blocks (rows 5..16383)

// ---------------- device scratch (static, allocation-free) ----------------
__device__ float  g_sd[TPAD];           // noise std-dev per padded time step
__device__ float  g_s[TT * BB];         // FIR output s[t][b]
__device__ float4 g_u[NBLK * BB];       // zero-state end states u_k per (block,col)

struct FIX {
    float m[5 * 16];      // M^0..M^4 row-major 4x4, M = A^LBLK
    float h[4 * LBLK];    // zero-input impulse tables h_c[i]
};

// ---------------- kernel 1: noise std-dev per time step ----------------
__global__ __launch_bounds__(128) void k_sd(const float* __restrict__ sig,
                                            float c1, float addc) {
    int t = blockIdx.x;
    float sum = 0.f;
    if (t >= 4) {
        const float4* row = (const float4*)(sig + (size_t)(t - 4) * BB);
        float4 v = row[threadIdx.x];
        sum = (v.x + v.y) + (v.z + v.w);
    }
    #pragma unroll
    for (int o = 16; o; o >>= 1) sum += __shfl_down_sync(0xffffffffu, sum, o);
    __shared__ float red[4];
    if ((threadIdx.x & 31) == 0) red[threadIdx.x >> 5] = sum;
    __syncthreads();
    if (threadIdx.x == 0) {
        float tot = (red[0] + red[1]) + (red[2] + red[3]);
        g_sd[t] = sqrtf(fmaf(c1, tot * (1.f / 512.f), addc));
    }
}

// ---------------- kernel 2: xn + 5-tap FIR -> s[t][b]  (also out rows 0..4) ----------------
__global__ __launch_bounds__(256) void k_fir(const float* __restrict__ sig,
                                             const float* __restrict__ noise,
                                             float* __restrict__ out,
                                             float b0, float b1, float b2, float b3, float b4) {
    __shared__ float nz[32][69];
    __shared__ float sg[68][33];
    __shared__ float sds[68];
    int tx = threadIdx.x, ty = threadIdx.y;
    int col0 = blockIdx.x * 32;
    int t0   = blockIdx.y * 64;

    #pragma unroll
    for (int i = 0; i < 4; i++) {
        int c = ty * 4 + i;
        const float* nrow = noise + (size_t)(col0 + c) * TPAD + t0;
        for (int j = tx; j < 68; j += 32) nz[c][j] = nrow[j];
    }
    for (int r = ty; r < 68; r += 8) {
        int trow = t0 - 4 + r;
        sg[r][tx] = (trow >= 0) ? sig[(size_t)trow * BB + col0 + tx] : 0.f;
    }
    int tid = ty * 32 + tx;
    if (tid < 68) sds[tid] = g_sd[t0 + tid];
    __syncthreads();

    #pragma unroll
    for (int i = 0; i < 8; i++) {
        int tt = ty + 8 * i;
        float x0 = fmaf(sds[tt + 0], nz[tx][tt + 0], sg[tt + 0][tx]);
        float x1 = fmaf(sds[tt + 1], nz[tx][tt + 1], sg[tt + 1][tx]);
        float x2 = fmaf(sds[tt + 2], nz[tx][tt + 2], sg[tt + 2][tx]);
        float x3 = fmaf(sds[tt + 3], nz[tx][tt + 3], sg[tt + 3][tx]);
        float x4 = fmaf(sds[tt + 4], nz[tx][tt + 4], sg[tt + 4][tx]);
        float acc = b0 * x0;
        acc = fmaf(b1, x1, acc);
        acc = fmaf(b2, x2, acc);
        acc = fmaf(b3, x3, acc);
        acc = fmaf(b4, x4, acc);
        int t = t0 + tt;
        g_s[(size_t)t * BB + col0 + tx] = acc;
        if (t < 5) out[(size_t)t * BB + col0 + tx] = acc;
    }
}

// ---------------- pass A: zero-state in-block IIR -> out (y^zs), end-state -> g_u ----------------
__global__ __launch_bounds__(256) void k_zs(float* __restrict__ out,
                                            float na1, float na2, float na3, float na4) {
    int tx = threadIdx.x, ty = threadIdx.y;
    int col = blockIdx.x * 32 + tx;
    int k   = blockIdx.y * 8 + ty;

    float y1 = 0.f, y2 = 0.f, y3 = 0.f, y4 = 0.f;
    int n0 = 5 + LBLK * k;
    int nst = min(LBLK, TT - n0);          // 128 except last block (123)
    const float* sp = g_s + (size_t)n0 * BB + col;
    float*       op = out + (size_t)n0 * BB + col;
    #pragma unroll 8
    for (int i = 0; i < nst; i++) {
        float sv = sp[(size_t)i * BB];
        float t = fmaf(na4, y4, sv);
        t = fmaf(na3, y3, t);
        t = fmaf(na2, y2, t);
        float y = fmaf(na1, y1, t);
        op[(size_t)i * BB] = y;
        y4 = y3; y3 = y2; y2 = y1; y1 = y;
    }
    g_u[k * BB + col] = make_float4(y1, y2, y3, y4);
}

// ---------------- pass B: zero-input correction (streaming RMW) ----------------
// v_k = sum_{j=0}^{min(4,k)} M^j * u~_{k-1-j}, u~_{-1} = v_0 (from s rows 1..4)
// out[n0+i] += h0[i]*v.x + h1[i]*v.y + h2[i]*v.z + h3[i]*v.w
__global__ __launch_bounds__(256) void k_fix(float* __restrict__ out, FIX P) {
    int tx = threadIdx.x, ty = threadIdx.y;
    int col = blockIdx.x * 32 + tx;
    int k   = blockIdx.y;

    float v0 = 0.f, v1 = 0.f, v2 = 0.f, v3 = 0.f;
    #pragma unroll
    for (int j = 0; j <= 4; j++) {
        if (j > k) break;
        int idx = k - 1 - j;
        float4 s4;
        if (idx >= 0) {
            s4 = g_u[idx * BB + col];
        } else {
            s4 = make_float4(g_s[4 * BB + col], g_s[3 * BB + col],
                             g_s[2 * BB + col], g_s[1 * BB + col]);
        }
        const float* m = P.m + j * 16;
        v0 += m[0]  * s4.x + m[1]  * s4.y + m[2]  * s4.z + m[3]  * s4.w;
        v1 += m[4]  * s4.x + m[5]  * s4.y + m[6]  * s4.z + m[7]  * s4.w;
        v2 += m[8]  * s4.x + m[9]  * s4.y + m[10] * s4.z + m[11] * s4.w;
        v3 += m[12] * s4.x + m[13] * s4.y + m[14] * s4.z + m[15] * s4.w;
    }

    int n0 = 5 + LBLK * k;
    int nst = min(LBLK, TT - n0);
    float* op = out + (size_t)n0 * BB + col;
    #pragma unroll
    for (int step = 0; step < LBLK / 8; step++) {
        int i = ty + 8 * step;
        if (i >= nst) break;
        float add = P.h[0 * LBLK + i] * v0;
        add = fmaf(P.h[1 * LBLK + i], v1, add);
        add = fmaf(P.h[2 * LBLK + i], v2, add);
        add = fmaf(P.h[3 * LBLK + i], v3, add);
        op[(size_t)i * BB] += add;
    }
}

// ---------------- host: Butterworth design (exact replica of reference, f64) ----------------
static void compute_butter(double* bc, double* ac) {
    const double PI = 3.14159265358979323846264338327950288;
    const int order = 4;
    const double wn = 25e9 / (0.5 / 1e-12);   // 0.05
    double warped = 4.0 * tan(PI * wn / 2.0);
    std::complex<double> p[4];
    for (int k = 1; k <= order; k++) {
        double ang = PI * (2.0 * k + order - 1.0) / (2.0 * order);
        p[k - 1] = warped * std::complex<double>(cos(ang), sin(ang));
    }
    double gain = warped * warped * warped * warped;
    std::complex<double> fs2(4.0, 0.0);
    std::complex<double> pz[4], prod(1.0, 0.0);
    for (int i = 0; i < 4; i++) { pz[i] = (fs2 + p[i]) / (fs2 - p[i]); prod *= (fs2 - p[i]); }
    double gz = gain * std::real(std::complex<double>(1.0, 0.0) / prod);
    const double binom[5] = {1, 4, 6, 4, 1};
    for (int i = 0; i < 5; i++) bc[i] = gz * binom[i];
    std::complex<double> c[5] = {{1,0},{0,0},{0,0},{0,0},{0,0}};
    for (int i = 0; i < 4; i++)
        for (int j = i + 1; j >= 1; j--)
            c[j] -= pz[i] * c[j - 1];
    for (int i = 0; i < 5; i++) ac[i] = std::real(c[i]);
}

extern "C" void kernel_launch(void* const* d_in, const int* in_sizes, int n_in,
                              void* d_out, int out_size) {
    const float* sig   = (const float*)d_in[0];   // (16384, 512) f32
    const float* noise = (const float*)d_in[1];   // (512, 1, 16388) f32
    float* out = (float*)d_out;                   // (16384, 512) f32

    double bc[5], ac[5];
    compute_butter(bc, ac);

    // zero-input impulse tables h_c (f64): state order [y1,y2,y3,y4], init = e_c
    static FIX fx;   // static: stable across graph replays (values identical every call)
    for (int c = 0; c < 4; c++) {
        double y1 = (c == 0), y2 = (c == 1), y3 = (c == 2), y4 = (c == 3);
        for (int i = 0; i < LBLK; i++) {
            double y = -(ac[1] * y1 + ac[2] * y2 + ac[3] * y3 + ac[4] * y4);
            fx.h[c * LBLK + i] = (float)y;
            y4 = y3; y3 = y2; y2 = y1; y1 = y;
        }
    }
    // M = A^LBLK columns via zero-input simulation; then powers M^0..M^4 (f64)
    double M[16], Pj[16], tmp[16];
    for (int c = 0; c < 4; c++) {
        double y1 = (c == 0), y2 = (c == 1), y3 = (c == 2), y4 = (c == 3);
        for (int it = 0; it < LBLK; it++) {
            double y = -(ac[1] * y1 + ac[2] * y2 + ac[3] * y3 + ac[4] * y4);
            y4 = y3; y3 = y2; y2 = y1; y1 = y;
        }
        M[0 * 4 + c] = y1; M[1 * 4 + c] = y2; M[2 * 4 + c] = y3; M[3 * 4 + c] = y4;
    }
    for (int i = 0; i < 16; i++) Pj[i] = (i % 5 == 0) ? 1.0 : 0.0;  // identity
    for (int j = 0; j <= 4; j++) {
        for (int i = 0; i < 16; i++) fx.m[j * 16 + i] = (float)Pj[i];
        // Pj = Pj * M
        for (int r = 0; r < 4; r++)
            for (int cc = 0; cc < 4; cc++) {
                double acc = 0.0;
                for (int t = 0; t < 4; t++) acc += Pj[r * 4 + t] * M[t * 4 + cc];
                tmp[r * 4 + cc] = acc;
            }
        for (int i = 0; i < 16; i++) Pj[i] = tmp[i];
    }

    const double Qc = 1.602176563e-19, KBc = 1.3806488e-23, Tk = 300.0;
    const double BR = 5e10, DARK = 1e-10, RL = 1e6;
    double C1  = 2.0 * Qc * BR;
    double ADD = C1 * DARK + 4.0 * KBc * Tk * BR / RL;

    k_sd <<<TPAD, 128>>>(sig, (float)C1, (float)ADD);
    k_fir<<<dim3(16, 256), dim3(32, 8)>>>(sig, noise, out,
            (float)bc[0], (float)bc[1], (float)bc[2], (float)bc[3], (float)bc[4]);
    k_zs <<<dim3(16, 16), dim3(32, 8)>>>(out,
            (float)(-ac[1]), (float)(-ac[2]), (float)(-ac[3]), (float)(-ac[4]));
    k_fix<<<dim3(16, NBLK), dim3(32, 8)>>>(out, fx);
}

// round 7
// speedup vs baseline: 1.7695x; 1.7695x over previous
#include <cuda_runtime.h>
#include <math.h>
#include <complex>

// ---------------- problem constants ----------------
#define TT    16384          // time steps (output rows)
#define BB    512            // batch columns
#define TPAD  16388          // TT + K - 1 (K = 5)
#define LBLK  64             // IIR parallel block length
#define NBLK  256            // number of IIR blocks (rows 5..16383)

// ---------------- device scratch (static, allocation-free) ----------------
__device__ float  g_sd[TPAD];           // noise std-dev per padded time step
__device__ float  g_s[TT * BB];         // FIR output s[t][b]
__device__ float4 g_u[NBLK * BB];       // zero-state end states per (block,col)

struct FIX {
    float m[5 * 16];      // M^0..M^4 row-major 4x4, M = A^LBLK
};

// ---------------- kernel 1: noise std-dev per time step (1 warp per row) ----------------
__global__ __launch_bounds__(256) void k_sd(const float* __restrict__ sig,
                                            float c1, float addc) {
    int lane = threadIdx.x & 31;
    int t = blockIdx.x * 8 + (threadIdx.x >> 5);
    if (t >= TPAD) return;
    float sum = 0.f;
    if (t >= 4) {
        const float4* row = (const float4*)(sig + (size_t)(t - 4) * BB);
        float4 a = row[lane], b = row[lane + 32], c = row[lane + 64], d = row[lane + 96];
        sum = ((a.x + a.y) + (a.z + a.w)) + ((b.x + b.y) + (b.z + b.w))
            + ((c.x + c.y) + (c.z + c.w)) + ((d.x + d.y) + (d.z + d.w));
    }
    #pragma unroll
    for (int o = 16; o; o >>= 1) sum += __shfl_down_sync(0xffffffffu, sum, o);
    if (lane == 0)
        g_sd[t] = sqrtf(fmaf(c1, sum * (1.f / 512.f), addc));
}

// ---------------- kernel 2: xn + 5-tap FIR -> s[t][b]  (also out rows 0..4) ----------------
__global__ __launch_bounds__(256) void k_fir(const float* __restrict__ sig,
                                             const float* __restrict__ noise,
                                             float* __restrict__ out,
                                             float b0, float b1, float b2, float b3, float b4) {
    __shared__ float nz[32][69];   // [col][j], stride 69 -> conflict-free transpose reads
    __shared__ float sg[68][33];   // [j][col]
    __shared__ float sds[68];
    int tx = threadIdx.x, ty = threadIdx.y;
    int col0 = blockIdx.x * 32;
    int t0   = blockIdx.y * 64;

    #pragma unroll
    for (int i = 0; i < 4; i++) {
        int c = ty * 4 + i;
        const float* nrow = noise + (size_t)(col0 + c) * TPAD + t0;
        for (int j = tx; j < 68; j += 32) nz[c][j] = nrow[j];
    }
    for (int r = ty; r < 68; r += 8) {
        int trow = t0 - 4 + r;
        sg[r][tx] = (trow >= 0) ? sig[(size_t)trow * BB + col0 + tx] : 0.f;
    }
    int tid = ty * 32 + tx;
    if (tid < 68) sds[tid] = g_sd[t0 + tid];
    __syncthreads();

    #pragma unroll
    for (int i = 0; i < 8; i++) {
        int tt = ty + 8 * i;
        float x0 = fmaf(sds[tt + 0], nz[tx][tt + 0], sg[tt + 0][tx]);
        float x1 = fmaf(sds[tt + 1], nz[tx][tt + 1], sg[tt + 1][tx]);
        float x2 = fmaf(sds[tt + 2], nz[tx][tt + 2], sg[tt + 2][tx]);
        float x3 = fmaf(sds[tt + 3], nz[tx][tt + 3], sg[tt + 3][tx]);
        float x4 = fmaf(sds[tt + 4], nz[tx][tt + 4], sg[tt + 4][tx]);
        float acc = b0 * x0;
        acc = fmaf(b1, x1, acc);
        acc = fmaf(b2, x2, acc);
        acc = fmaf(b3, x3, acc);
        acc = fmaf(b4, x4, acc);
        int t = t0 + tt;
        g_s[(size_t)t * BB + col0 + tx] = acc;
        if (t < 5) out[(size_t)t * BB + col0 + tx] = acc;
    }
}

// ---------------- pass A: zero-state in-block IIR -> end-state only ----------------
__global__ __launch_bounds__(256) void k_us(float na1, float na2, float na3, float na4) {
    int tx = threadIdx.x, ty = threadIdx.y;
    int col = blockIdx.x * 32 + tx;
    int k   = blockIdx.y * 8 + ty;

    float y1 = 0.f, y2 = 0.f, y3 = 0.f, y4 = 0.f;
    int n0 = 5 + LBLK * k;
    const float* sp = g_s + (size_t)n0 * BB + col;
    if (k != NBLK - 1) {
        #pragma unroll 16
        for (int i = 0; i < LBLK; i++) {
            float sv = sp[(size_t)i * BB];
            float t = fmaf(na4, y4, sv);
            t = fmaf(na3, y3, t);
            t = fmaf(na2, y2, t);
            float y = fmaf(na1, y1, t);
            y4 = y3; y3 = y2; y2 = y1; y1 = y;
        }
    } else {
        int nst = TT - n0;   // 59
        for (int i = 0; i < nst; i++) {
            float sv = sp[(size_t)i * BB];
            float t = fmaf(na4, y4, sv);
            t = fmaf(na3, y3, t);
            t = fmaf(na2, y2, t);
            float y = fmaf(na1, y1, t);
            y4 = y3; y3 = y2; y2 = y1; y1 = y;
        }
    }
    g_u[k * BB + col] = make_float4(y1, y2, y3, y4);
}

// ---------------- pass B: exact in-block IIR from reconstructed state, write out ----------------
// v_k = sum_{j=0}^{min(4,k)} M^j * u~_{k-1-j}, u~_{-1} = v_0 (from s rows 1..4)
__global__ __launch_bounds__(256) void k_iir(float* __restrict__ out, FIX P,
                                             float na1, float na2, float na3, float na4) {
    int tx = threadIdx.x, ty = threadIdx.y;
    int col = blockIdx.x * 32 + tx;
    int k   = blockIdx.y * 8 + ty;

    float y1 = 0.f, y2 = 0.f, y3 = 0.f, y4 = 0.f;
    #pragma unroll
    for (int j = 0; j <= 4; j++) {
        if (j > k) break;
        int idx = k - 1 - j;
        float4 s4;
        if (idx >= 0) {
            s4 = g_u[idx * BB + col];
        } else {
            s4 = make_float4(g_s[4 * BB + col], g_s[3 * BB + col],
                             g_s[2 * BB + col], g_s[1 * BB + col]);
        }
        const float* m = P.m + j * 16;
        y1 = fmaf(m[0],  s4.x, y1); y1 = fmaf(m[1],  s4.y, y1);
        y1 = fmaf(m[2],  s4.z, y1); y1 = fmaf(m[3],  s4.w, y1);
        y2 = fmaf(m[4],  s4.x, y2); y2 = fmaf(m[5],  s4.y, y2);
        y2 = fmaf(m[6],  s4.z, y2); y2 = fmaf(m[7],  s4.w, y2);
        y3 = fmaf(m[8],  s4.x, y3); y3 = fmaf(m[9],  s4.y, y3);
        y3 = fmaf(m[10], s4.z, y3); y3 = fmaf(m[11], s4.w, y3);
        y4 = fmaf(m[12], s4.x, y4); y4 = fmaf(m[13], s4.y, y4);
        y4 = fmaf(m[14], s4.z, y4); y4 = fmaf(m[15], s4.w, y4);
    }

    int n0 = 5 + LBLK * k;
    const float* sp = g_s + (size_t)n0 * BB + col;
    float*       op = out + (size_t)n0 * BB + col;
    if (k != NBLK - 1) {
        #pragma unroll 16
        for (int i = 0; i < LBLK; i++) {
            float sv = sp[(size_t)i * BB];
            float t = fmaf(na4, y4, sv);
            t = fmaf(na3, y3, t);
            t = fmaf(na2, y2, t);
            float y = fmaf(na1, y1, t);
            op[(size_t)i * BB] = y;
            y4 = y3; y3 = y2; y2 = y1; y1 = y;
        }
    } else {
        int nst = TT - n0;   // 59
        for (int i = 0; i < nst; i++) {
            float sv = sp[(size_t)i * BB];
            float t = fmaf(na4, y4, sv);
            t = fmaf(na3, y3, t);
            t = fmaf(na2, y2, t);
            float y = fmaf(na1, y1, t);
            op[(size_t)i * BB] = y;
            y4 = y3; y3 = y2; y2 = y1; y1 = y;
        }
    }
}

// ---------------- host: Butterworth design (exact replica of reference, f64) ----------------
static void compute_butter(double* bc, double* ac) {
    const double PI = 3.14159265358979323846264338327950288;
    const int order = 4;
    const double wn = 25e9 / (0.5 / 1e-12);   // 0.05
    double warped = 4.0 * tan(PI * wn / 2.0);
    std::complex<double> p[4];
    for (int k = 1; k <= order; k++) {
        double ang = PI * (2.0 * k + order - 1.0) / (2.0 * order);
        p[k - 1] = warped * std::complex<double>(cos(ang), sin(ang));
    }
    double gain = warped * warped * warped * warped;
    std::complex<double> fs2(4.0, 0.0);
    std::complex<double> pz[4], prod(1.0, 0.0);
    for (int i = 0; i < 4; i++) { pz[i] = (fs2 + p[i]) / (fs2 - p[i]); prod *= (fs2 - p[i]); }
    double gz = gain * std::real(std::complex<double>(1.0, 0.0) / prod);
    const double binom[5] = {1, 4, 6, 4, 1};
    for (int i = 0; i < 5; i++) bc[i] = gz * binom[i];
    std::complex<double> c[5] = {{1,0},{0,0},{0,0},{0,0},{0,0}};
    for (int i = 0; i < 4; i++)
        for (int j = i + 1; j >= 1; j--)
            c[j] -= pz[i] * c[j - 1];
    for (int i = 0; i < 5; i++) ac[i] = std::real(c[i]);
}

extern "C" void kernel_launch(void* const* d_in, const int* in_sizes, int n_in,
                              void* d_out, int out_size) {
    const float* sig   = (const float*)d_in[0];   // (16384, 512) f32
    const float* noise = (const float*)d_in[1];   // (512, 1, 16388) f32
    float* out = (float*)d_out;                   // (16384, 512) f32

    double bc[5], ac[5];
    compute_butter(bc, ac);

    // M = A^LBLK columns via zero-input simulation; then powers M^0..M^4 (f64)
    static FIX fx;
    double M[16], Pj[16], tmp[16];
    for (int c = 0; c < 4; c++) {
        double y1 = (c == 0), y2 = (c == 1), y3 = (c == 2), y4 = (c == 3);
        for (int it = 0; it < LBLK; it++) {
            double y = -(ac[1] * y1 + ac[2] * y2 + ac[3] * y3 + ac[4] * y4);
            y4 = y3; y3 = y2; y2 = y1; y1 = y;
        }
        M[0 * 4 + c] = y1; M[1 * 4 + c] = y2; M[2 * 4 + c] = y3; M[3 * 4 + c] = y4;
    }
    for (int i = 0; i < 16; i++) Pj[i] = (i % 5 == 0) ? 1.0 : 0.0;  // identity
    for (int j = 0; j <= 4; j++) {
        for (int i = 0; i < 16; i++) fx.m[j * 16 + i] = (float)Pj[i];
        for (int r = 0; r < 4; r++)
            for (int cc = 0; cc < 4; cc++) {
                double acc = 0.0;
                for (int t = 0; t < 4; t++) acc += Pj[r * 4 + t] * M[t * 4 + cc];
                tmp[r * 4 + cc] = acc;
            }
        for (int i = 0; i < 16; i++) Pj[i] = tmp[i];
    }

    const double Qc = 1.602176563e-19, KBc = 1.3806488e-23, Tk = 300.0;
    const double BR = 5e10, DARK = 1e-10, RL = 1e6;
    double C1  = 2.0 * Qc * BR;
    double ADD = C1 * DARK + 4.0 * KBc * Tk * BR / RL;

    float na1 = (float)(-ac[1]), na2 = (float)(-ac[2]);
    float na3 = (float)(-ac[3]), na4 = (float)(-ac[4]);

    k_sd <<<(TPAD + 7) / 8, 256>>>(sig, (float)C1, (float)ADD);
    k_fir<<<dim3(16, 256), dim3(32, 8)>>>(sig, noise, out,
            (float)bc[0], (float)bc[1], (float)bc[2], (float)bc[3], (float)bc[4]);
    k_us <<<dim3(16, 32), dim3(32, 8)>>>(na1, na2, na3, na4);
    k_iir<<<dim3(16, 32), dim3(32, 8)>>>(out, fx, na1, na2, na3, na4);
}

// round 8
// speedup vs baseline: 1.9124x; 1.0807x over previous
#include <cuda_runtime.h>
#include <math.h>
#include <complex>

// ---------------- problem constants ----------------
#define TT    16384          // time steps (output rows)
#define BB    512            // batch columns
#define TPAD  16388          // TT + K - 1 (K = 5)
#define NBLK  256            // IIR blocks: block 0 = rows 5..63, block k = rows 64k..64k+63

// ---------------- device scratch (static, allocation-free) ----------------
__device__ float  g_sd[TPAD];           // noise std-dev per padded time step
__device__ float  g_s[TT * BB];         // FIR output s[t][b]
__device__ float4 g_u[NBLK * BB];       // zero-state end states per (block,col)

struct FIX {
    float m[5 * 16];      // M^j (j=0..4), M = A^64, row-major 4x4   (applied to u)
    float ma[5 * 16];     // M^i * A^59 (i=0..4)                      (applied to v0, i=k-1)
};

// ---------------- kernel 1: noise std-dev per time step (1 warp per row) ----------------
__global__ __launch_bounds__(256) void k_sd(const float* __restrict__ sig,
                                            float c1, float addc) {
    int lane = threadIdx.x & 31;
    int t = blockIdx.x * 8 + (threadIdx.x >> 5);
    if (t >= TPAD) return;
    float sum = 0.f;
    if (t >= 4) {
        const float4* row = (const float4*)(sig + (size_t)(t - 4) * BB);
        float4 a = row[lane], b = row[lane + 32], c = row[lane + 64], d = row[lane + 96];
        sum = ((a.x + a.y) + (a.z + a.w)) + ((b.x + b.y) + (b.z + b.w))
            + ((c.x + c.y) + (c.z + c.w)) + ((d.x + d.y) + (d.z + d.w));
    }
    #pragma unroll
    for (int o = 16; o; o >>= 1) sum += __shfl_down_sync(0xffffffffu, sum, o);
    if (lane == 0)
        g_sd[t] = sqrtf(fmaf(c1, sum * (1.f / 512.f), addc));
}

// ---------------- kernel 2: xn + 5-tap FIR -> s[t][b], plus per-block zero-state scan ----------------
// Tile = 64 t-rows x 32 cols == one IIR block. After computing s, one warp runs the
// zero-state IIR over the tile (from smem) and writes the end-state u_k.
__global__ __launch_bounds__(256) void k_fir(const float* __restrict__ sig,
                                             const float* __restrict__ noise,
                                             float* __restrict__ out,
                                             float b0, float b1, float b2, float b3, float b4,
                                             float na1, float na2, float na3, float na4) {
    __shared__ float nz[32][69];   // noise [col][j], stride 69 -> conflict-free transpose
    __shared__ float sg[68][33];   // signal [j][col]
    __shared__ float st[64][33];   // s tile [t][col] for the zero-state scan
    __shared__ float sds[68];
    int tx = threadIdx.x, ty = threadIdx.y;
    int col0 = blockIdx.x * 32;
    int t0   = blockIdx.y * 64;

    #pragma unroll
    for (int i = 0; i < 4; i++) {
        int c = ty * 4 + i;
        const float* nrow = noise + (size_t)(col0 + c) * TPAD + t0;
        for (int j = tx; j < 68; j += 32) nz[c][j] = nrow[j];
    }
    for (int r = ty; r < 68; r += 8) {
        int trow = t0 - 4 + r;
        sg[r][tx] = (trow >= 0) ? sig[(size_t)trow * BB + col0 + tx] : 0.f;
    }
    int tid = ty * 32 + tx;
    if (tid < 68) sds[tid] = g_sd[t0 + tid];
    __syncthreads();

    #pragma unroll
    for (int i = 0; i < 8; i++) {
        int tt = ty + 8 * i;
        float x0 = fmaf(sds[tt + 0], nz[tx][tt + 0], sg[tt + 0][tx]);
        float x1 = fmaf(sds[tt + 1], nz[tx][tt + 1], sg[tt + 1][tx]);
        float x2 = fmaf(sds[tt + 2], nz[tx][tt + 2], sg[tt + 2][tx]);
        float x3 = fmaf(sds[tt + 3], nz[tx][tt + 3], sg[tt + 3][tx]);
        float x4 = fmaf(sds[tt + 4], nz[tx][tt + 4], sg[tt + 4][tx]);
        float acc = b0 * x0;
        acc = fmaf(b1, x1, acc);
        acc = fmaf(b2, x2, acc);
        acc = fmaf(b3, x3, acc);
        acc = fmaf(b4, x4, acc);
        int t = t0 + tt;
        g_s[(size_t)t * BB + col0 + tx] = acc;
        st[tt][tx] = acc;
        if (t < 5) out[(size_t)t * BB + col0 + tx] = acc;
    }
    __syncthreads();

    // zero-state scan by warp ty==0 (32 cols, serial over 64 (or 59) rows)
    if (ty == 0) {
        int k = blockIdx.y;
        float y1 = 0.f, y2 = 0.f, y3 = 0.f, y4 = 0.f;
        if (k == 0) {
            for (int i = 5; i < 64; i++) {
                float sv = st[i][tx];
                float t = fmaf(na4, y4, sv);
                t = fmaf(na3, y3, t);
                t = fmaf(na2, y2, t);
                float y = fmaf(na1, y1, t);
                y4 = y3; y3 = y2; y2 = y1; y1 = y;
            }
        } else {
            #pragma unroll 16
            for (int i = 0; i < 64; i++) {
                float sv = st[i][tx];
                float t = fmaf(na4, y4, sv);
                t = fmaf(na3, y3, t);
                t = fmaf(na2, y2, t);
                float y = fmaf(na1, y1, t);
                y4 = y3; y3 = y2; y2 = y1; y1 = y;
            }
        }
        g_u[k * BB + col0 + tx] = make_float4(y1, y2, y3, y4);
    }
}

// ---------------- pass B: exact in-block IIR from reconstructed state, write out ----------------
// v_k = sum_{j=0}^{min(4,k-1)} M^j u_{k-1-j} + (k<=5 ? M^{k-1} A^59 v0 : 0);  v_0 from s rows 1..4.
// Each thread handles 2 adjacent columns (float2) for 2x ILP.
__global__ __launch_bounds__(256) void k_iir(float* __restrict__ out, FIX P,
                                             float na1, float na2, float na3, float na4) {
    int tx = threadIdx.x, ty = threadIdx.y;
    int col = blockIdx.x * 64 + tx * 2;
    int k   = blockIdx.y * 8 + ty;

    float a1 = 0.f, a2 = 0.f, a3 = 0.f, a4 = 0.f;
    float b1 = 0.f, b2 = 0.f, b3 = 0.f, b4 = 0.f;

    if (k == 0) {
        a1 = g_s[4 * BB + col];     b1 = g_s[4 * BB + col + 1];
        a2 = g_s[3 * BB + col];     b2 = g_s[3 * BB + col + 1];
        a3 = g_s[2 * BB + col];     b3 = g_s[2 * BB + col + 1];
        a4 = g_s[1 * BB + col];     b4 = g_s[1 * BB + col + 1];
    } else {
        #pragma unroll
        for (int j = 0; j <= 4; j++) {
            int idx = k - 1 - j;
            if (idx < 0) break;
            float4 ua = g_u[idx * BB + col];
            float4 ub = g_u[idx * BB + col + 1];
            const float* m = P.m + j * 16;
            a1 = fmaf(m[0],  ua.x, a1); a1 = fmaf(m[1],  ua.y, a1);
            a1 = fmaf(m[2],  ua.z, a1); a1 = fmaf(m[3],  ua.w, a1);
            a2 = fmaf(m[4],  ua.x, a2); a2 = fmaf(m[5],  ua.y, a2);
            a2 = fmaf(m[6],  ua.z, a2); a2 = fmaf(m[7],  ua.w, a2);
            a3 = fmaf(m[8],  ua.x, a3); a3 = fmaf(m[9],  ua.y, a3);
            a3 = fmaf(m[10], ua.z, a3); a3 = fmaf(m[11], ua.w, a3);
            a4 = fmaf(m[12], ua.x, a4); a4 = fmaf(m[13], ua.y, a4);
            a4 = fmaf(m[14], ua.z, a4); a4 = fmaf(m[15], ua.w, a4);
            b1 = fmaf(m[0],  ub.x, b1); b1 = fmaf(m[1],  ub.y, b1);
            b1 = fmaf(m[2],  ub.z, b1); b1 = fmaf(m[3],  ub.w, b1);
            b2 = fmaf(m[4],  ub.x, b2); b2 = fmaf(m[5],  ub.y, b2);
            b2 = fmaf(m[6],  ub.z, b2); b2 = fmaf(m[7],  ub.w, b2);
            b3 = fmaf(m[8],  ub.x, b3); b3 = fmaf(m[9],  ub.y, b3);
            b3 = fmaf(m[10], ub.z, b3); b3 = fmaf(m[11], ub.w, b3);
            b4 = fmaf(m[12], ub.x, b4); b4 = fmaf(m[13], ub.y, b4);
            b4 = fmaf(m[14], ub.z, b4); b4 = fmaf(m[15], ub.w, b4);
        }
        if (k <= 5) {
            const float* m = P.ma + (k - 1) * 16;
            float vax = g_s[4 * BB + col], vbx = g_s[4 * BB + col + 1];
            float vay = g_s[3 * BB + col], vby = g_s[3 * BB + col + 1];
            float vaz = g_s[2 * BB + col], vbz = g_s[2 * BB + col + 1];
            float vaw = g_s[1 * BB + col], vbw = g_s[1 * BB + col + 1];
            a1 = fmaf(m[0],  vax, a1); a1 = fmaf(m[1],  vay, a1);
            a1 = fmaf(m[2],  vaz, a1); a1 = fmaf(m[3],  vaw, a1);
            a2 = fmaf(m[4],  vax, a2); a2 = fmaf(m[5],  vay, a2);
            a2 = fmaf(m[6],  vaz, a2); a2 = fmaf(m[7],  vaw, a2);
            a3 = fmaf(m[8],  vax, a3); a3 = fmaf(m[9],  vay, a3);
            a3 = fmaf(m[10], vaz, a3); a3 = fmaf(m[11], vaw, a3);
            a4 = fmaf(m[12], vax, a4); a4 = fmaf(m[13], vay, a4);
            a4 = fmaf(m[14], vaz, a4); a4 = fmaf(m[15], vaw, a4);
            b1 = fmaf(m[0],  vbx, b1); b1 = fmaf(m[1],  vby, b1);
            b1 = fmaf(m[2],  vbz, b1); b1 = fmaf(m[3],  vbw, b1);
            b2 = fmaf(m[4],  vbx, b2); b2 = fmaf(m[5],  vby, b2);
            b2 = fmaf(m[6],  vbz, b2); b2 = fmaf(m[7],  vbw, b2);
            b3 = fmaf(m[8],  vbx, b3); b3 = fmaf(m[9],  vby, b3);
            b3 = fmaf(m[10], vbz, b3); b3 = fmaf(m[11], vbw, b3);
            b4 = fmaf(m[12], vbx, b4); b4 = fmaf(m[13], vby, b4);
            b4 = fmaf(m[14], vbz, b4); b4 = fmaf(m[15], vbw, b4);
        }
    }

    int n0 = (k == 0) ? 5 : 64 * k;
    const float* sp = g_s + (size_t)n0 * BB + col;
    float*       op = out + (size_t)n0 * BB + col;
    if (k == 0) {
        for (int i = 0; i < 59; i++) {
            float2 sv = *(const float2*)(sp + (size_t)i * BB);
            float ta = fmaf(na4, a4, sv.x);
            ta = fmaf(na3, a3, ta);
            ta = fmaf(na2, a2, ta);
            float ya = fmaf(na1, a1, ta);
            float tb = fmaf(na4, b4, sv.y);
            tb = fmaf(na3, b3, tb);
            tb = fmaf(na2, b2, tb);
            float yb = fmaf(na1, b1, tb);
            *(float2*)(op + (size_t)i * BB) = make_float2(ya, yb);
            a4 = a3; a3 = a2; a2 = a1; a1 = ya;
            b4 = b3; b3 = b2; b2 = b1; b1 = yb;
        }
    } else {
        #pragma unroll 16
        for (int i = 0; i < 64; i++) {
            float2 sv = *(const float2*)(sp + (size_t)i * BB);
            float ta = fmaf(na4, a4, sv.x);
            ta = fmaf(na3, a3, ta);
            ta = fmaf(na2, a2, ta);
            float ya = fmaf(na1, a1, ta);
            float tb = fmaf(na4, b4, sv.y);
            tb = fmaf(na3, b3, tb);
            tb = fmaf(na2, b2, tb);
            float yb = fmaf(na1, b1, tb);
            *(float2*)(op + (size_t)i * BB) = make_float2(ya, yb);
            a4 = a3; a3 = a2; a2 = a1; a1 = ya;
            b4 = b3; b3 = b2; b2 = b1; b1 = yb;
        }
    }
}

// ---------------- host: Butterworth design (exact replica of reference, f64) ----------------
static void compute_butter(double* bc, double* ac) {
    const double PI = 3.14159265358979323846264338327950288;
    const int order = 4;
    const double wn = 25e9 / (0.5 / 1e-12);   // 0.05
    double warped = 4.0 * tan(PI * wn / 2.0);
    std::complex<double> p[4];
    for (int k = 1; k <= order; k++) {
        double ang = PI * (2.0 * k + order - 1.0) / (2.0 * order);
        p[k - 1] = warped * std::complex<double>(cos(ang), sin(ang));
    }
    double gain = warped * warped * warped * warped;
    std::complex<double> fs2(4.0, 0.0);
    std::complex<double> pz[4], prod(1.0, 0.0);
    for (int i = 0; i < 4; i++) { pz[i] = (fs2 + p[i]) / (fs2 - p[i]); prod *= (fs2 - p[i]); }
    double gz = gain * std::real(std::complex<double>(1.0, 0.0) / prod);
    const double binom[5] = {1, 4, 6, 4, 1};
    for (int i = 0; i < 5; i++) bc[i] = gz * binom[i];
    std::complex<double> c[5] = {{1,0},{0,0},{0,0},{0,0},{0,0}};
    for (int i = 0; i < 4; i++)
        for (int j = i + 1; j >= 1; j--)
            c[j] -= pz[i] * c[j - 1];
    for (int i = 0; i < 5; i++) ac[i] = std::real(c[i]);
}

// A^n (companion of the IIR state [y1,y2,y3,y4]) via column simulation, f64
static void apow(const double* ac, int n, double* A) {
    for (int c = 0; c < 4; c++) {
        double y1 = (c == 0), y2 = (c == 1), y3 = (c == 2), y4 = (c == 3);
        for (int it = 0; it < n; it++) {
            double y = -(ac[1] * y1 + ac[2] * y2 + ac[3] * y3 + ac[4] * y4);
            y4 = y3; y3 = y2; y2 = y1; y1 = y;
        }
        A[0 * 4 + c] = y1; A[1 * 4 + c] = y2; A[2 * 4 + c] = y3; A[3 * 4 + c] = y4;
    }
}

static void matmul4(const double* X, const double* Y, double* Z) {
    for (int r = 0; r < 4; r++)
        for (int c = 0; c < 4; c++) {
            double acc = 0.0;
            for (int t = 0; t < 4; t++) acc += X[r * 4 + t] * Y[t * 4 + c];
            Z[r * 4 + c] = acc;
        }
}

extern "C" void kernel_launch(void* const* d_in, const int* in_sizes, int n_in,
                              void* d_out, int out_size) {
    const float* sig   = (const float*)d_in[0];   // (16384, 512) f32
    const float* noise = (const float*)d_in[1];   // (512, 1, 16388) f32
    float* out = (float*)d_out;                   // (16384, 512) f32

    double bc[5], ac[5];
    compute_butter(bc, ac);

    static FIX fx;
    double A59[16], A64[16], Mj[16], tmp[16];
    apow(ac, 59, A59);
    apow(ac, 64, A64);
    for (int i = 0; i < 16; i++) Mj[i] = (i % 5 == 0) ? 1.0 : 0.0;   // M^0 = I
    for (int j = 0; j <= 4; j++) {
        for (int i = 0; i < 16; i++) fx.m[j * 16 + i] = (float)Mj[i];
        matmul4(Mj, A59, tmp);                   // ma[j] = M^j * A^59
        for (int i = 0; i < 16; i++) fx.ma[j * 16 + i] = (float)tmp[i];
        matmul4(Mj, A64, tmp);                   // Mj = M^{j+1}
        for (int i = 0; i < 16; i++) Mj[i] = tmp[i];
    }

    const double Qc = 1.602176563e-19, KBc = 1.3806488e-23, Tk = 300.0;
    const double BR = 5e10, DARK = 1e-10, RL = 1e6;
    double C1  = 2.0 * Qc * BR;
    double ADD = C1 * DARK + 4.0 * KBc * Tk * BR / RL;

    float na1 = (float)(-ac[1]), na2 = (float)(-ac[2]);
    float na3 = (float)(-ac[3]), na4 = (float)(-ac[4]);

    k_sd <<<(TPAD + 7) / 8, 256>>>(sig, (float)C1, (float)ADD);
    k_fir<<<dim3(16, 256), dim3(32, 8)>>>(sig, noise, out,
            (float)bc[0], (float)bc[1], (float)bc[2], (float)bc[3], (float)bc[4],
            na1, na2, na3, na4);
    k_iir<<<dim3(8, 32), dim3(32, 8)>>>(out, fx, na1, na2, na3, na4);
}

// round 9
// speedup vs baseline: 2.0389x; 1.0661x over previous
#include <cuda_runtime.h>
#include <math.h>
#include <complex>

// ---------------- problem constants ----------------
#define TT    16384          // time steps (output rows)
#define BB    512            // batch columns
#define TPAD  16388          // TT + K - 1 (K = 5)
#define NBLK  256            // IIR blocks: block 0 = rows 5..63, block k = rows 64k..64k+63

// ---------------- device scratch (static, allocation-free) ----------------
__device__ float  g_sd[TPAD];           // noise std-dev per padded time step
__device__ float  g_s[TT * BB];         // FIR output s[t][b]
__device__ float4 g_u[NBLK * BB];       // zero-state end states per (block,col)

struct FIX {
    float m[5 * 16];      // M^j (j=0..4), M = A^64, row-major 4x4   (applied to u)
    float ma[5 * 16];     // M^i * A^59 (i=0..4)                      (applied to v0, i=k-1)
};

// ---------------- kernel 1: noise std-dev, 2 rows per warp (8 loads in flight) ----------------
__global__ __launch_bounds__(256) void k_sd(const float* __restrict__ sig,
                                            float c1, float addc) {
    int lane = threadIdx.x & 31;
    int t0 = blockIdx.x * 16 + (threadIdx.x >> 5) * 2;
    if (t0 >= TPAD) return;
    float s0 = 0.f, s1 = 0.f;
    if (t0 >= 4) {
        const float4* r0 = (const float4*)(sig + (size_t)(t0 - 4) * BB);
        float4 a = r0[lane], b = r0[lane + 32], c = r0[lane + 64], d = r0[lane + 96];
        s0 = ((a.x + a.y) + (a.z + a.w)) + ((b.x + b.y) + (b.z + b.w))
           + ((c.x + c.y) + (c.z + c.w)) + ((d.x + d.y) + (d.z + d.w));
    }
    int t1 = t0 + 1;
    if (t1 >= 4 && t1 < TPAD) {
        const float4* r1 = (const float4*)(sig + (size_t)(t1 - 4) * BB);
        float4 a = r1[lane], b = r1[lane + 32], c = r1[lane + 64], d = r1[lane + 96];
        s1 = ((a.x + a.y) + (a.z + a.w)) + ((b.x + b.y) + (b.z + b.w))
           + ((c.x + c.y) + (c.z + c.w)) + ((d.x + d.y) + (d.z + d.w));
    }
    #pragma unroll
    for (int o = 16; o; o >>= 1) {
        s0 += __shfl_down_sync(0xffffffffu, s0, o);
        s1 += __shfl_down_sync(0xffffffffu, s1, o);
    }
    if (lane == 0) {
        g_sd[t0] = sqrtf(fmaf(c1, s0 * (1.f / 512.f), addc));
        if (t1 < TPAD) g_sd[t1] = sqrtf(fmaf(c1, s1 * (1.f / 512.f), addc));
    }
}

// ---------------- kernel 2: xn + 5-tap FIR -> s[t][b], plus per-block zero-state scan ----------------
// Thread (tx,ty) computes 8 CONSECUTIVE rows tt = 8*ty + i -> one 12-wide x window,
// 36 smem loads per thread instead of 120.
__global__ __launch_bounds__(256) void k_fir(const float* __restrict__ sig,
                                             const float* __restrict__ noise,
                                             float* __restrict__ out,
                                             float b0, float b1, float b2, float b3, float b4,
                                             float na1, float na2, float na3, float na4) {
    __shared__ float nz[32][69];   // noise [col][j], stride 69 -> conflict-free transpose
    __shared__ float sg[68][33];   // signal [j][col]
    __shared__ float st[64][33];   // s tile [t][col] for the zero-state scan
    __shared__ float sds[68];
    int tx = threadIdx.x, ty = threadIdx.y;
    int col0 = blockIdx.x * 32;
    int t0   = blockIdx.y * 64;

    #pragma unroll
    for (int i = 0; i < 4; i++) {
        int c = ty * 4 + i;
        const float* nrow = noise + (size_t)(col0 + c) * TPAD + t0;
        for (int j = tx; j < 68; j += 32) nz[c][j] = nrow[j];
    }
    for (int r = ty; r < 68; r += 8) {
        int trow = t0 - 4 + r;
        sg[r][tx] = (trow >= 0) ? sig[(size_t)trow * BB + col0 + tx] : 0.f;
    }
    int tid = ty * 32 + tx;
    if (tid < 68) sds[tid] = g_sd[t0 + tid];
    __syncthreads();

    // 12-value window x[8ty .. 8ty+11]
    float xv[12];
    #pragma unroll
    for (int j = 0; j < 12; j++) {
        int jj = 8 * ty + j;
        xv[j] = fmaf(sds[jj], nz[tx][jj], sg[jj][tx]);
    }
    #pragma unroll
    for (int i = 0; i < 8; i++) {
        float acc = b0 * xv[i];
        acc = fmaf(b1, xv[i + 1], acc);
        acc = fmaf(b2, xv[i + 2], acc);
        acc = fmaf(b3, xv[i + 3], acc);
        acc = fmaf(b4, xv[i + 4], acc);
        int tt = 8 * ty + i;
        int t = t0 + tt;
        g_s[(size_t)t * BB + col0 + tx] = acc;
        st[tt][tx] = acc;
        if (t < 5) out[(size_t)t * BB + col0 + tx] = acc;
    }
    __syncthreads();

    // zero-state scan by warp ty==0 (32 cols, serial over 64 (or 59) rows)
    if (ty == 0) {
        int k = blockIdx.y;
        float y1 = 0.f, y2 = 0.f, y3 = 0.f, y4 = 0.f;
        if (k == 0) {
            for (int i = 5; i < 64; i++) {
                float sv = st[i][tx];
                float t = fmaf(na4, y4, sv);
                t = fmaf(na3, y3, t);
                t = fmaf(na2, y2, t);
                float y = fmaf(na1, y1, t);
                y4 = y3; y3 = y2; y2 = y1; y1 = y;
            }
        } else {
            #pragma unroll 16
            for (int i = 0; i < 64; i++) {
                float sv = st[i][tx];
                float t = fmaf(na4, y4, sv);
                t = fmaf(na3, y3, t);
                t = fmaf(na2, y2, t);
                float y = fmaf(na1, y1, t);
                y4 = y3; y3 = y2; y2 = y1; y1 = y;
            }
        }
        g_u[k * BB + col0 + tx] = make_float4(y1, y2, y3, y4);
    }
}

// ---------------- pass B: exact in-block IIR from reconstructed state, write out ----------------
// v_k = sum_{j=0}^{min(4,k-1)} M^j u_{k-1-j} + (k<=5 ? M^{k-1} A^59 v0 : 0);  v_0 from s rows 1..4.
// Each thread handles 2 adjacent columns (float2) for 2x ILP.
__global__ __launch_bounds__(256) void k_iir(float* __restrict__ out, FIX P,
                                             float na1, float na2, float na3, float na4) {
    int tx = threadIdx.x, ty = threadIdx.y;
    int col = blockIdx.x * 64 + tx * 2;
    int k   = blockIdx.y * 8 + ty;

    float a1 = 0.f, a2 = 0.f, a3 = 0.f, a4 = 0.f;
    float b1 = 0.f, b2 = 0.f, b3 = 0.f, b4 = 0.f;

    if (k == 0) {
        a1 = g_s[4 * BB + col];     b1 = g_s[4 * BB + col + 1];
        a2 = g_s[3 * BB + col];     b2 = g_s[3 * BB + col + 1];
        a3 = g_s[2 * BB + col];     b3 = g_s[2 * BB + col + 1];
        a4 = g_s[1 * BB + col];     b4 = g_s[1 * BB + col + 1];
    } else {
        #pragma unroll
        for (int j = 0; j <= 4; j++) {
            int idx = k - 1 - j;
            if (idx < 0) break;
            float4 ua = g_u[idx * BB + col];
            float4 ub = g_u[idx * BB + col + 1];
            const float* m = P.m + j * 16;
            a1 = fmaf(m[0],  ua.x, a1); a1 = fmaf(m[1],  ua.y, a1);
            a1 = fmaf(m[2],  ua.z, a1); a1 = fmaf(m[3],  ua.w, a1);
            a2 = fmaf(m[4],  ua.x, a2); a2 = fmaf(m[5],  ua.y, a2);
            a2 = fmaf(m[6],  ua.z, a2); a2 = fmaf(m[7],  ua.w, a2);
            a3 = fmaf(m[8],  ua.x, a3); a3 = fmaf(m[9],  ua.y, a3);
            a3 = fmaf(m[10], ua.z, a3); a3 = fmaf(m[11], ua.w, a3);
            a4 = fmaf(m[12], ua.x, a4); a4 = fmaf(m[13], ua.y, a4);
            a4 = fmaf(m[14], ua.z, a4); a4 = fmaf(m[15], ua.w, a4);
            b1 = fmaf(m[0],  ub.x, b1); b1 = fmaf(m[1],  ub.y, b1);
            b1 = fmaf(m[2],  ub.z, b1); b1 = fmaf(m[3],  ub.w, b1);
            b2 = fmaf(m[4],  ub.x, b2); b2 = fmaf(m[5],  ub.y, b2);
            b2 = fmaf(m[6],  ub.z, b2); b2 = fmaf(m[7],  ub.w, b2);
            b3 = fmaf(m[8],  ub.x, b3); b3 = fmaf(m[9],  ub.y, b3);
            b3 = fmaf(m[10], ub.z, b3); b3 = fmaf(m[11], ub.w, b3);
            b4 = fmaf(m[12], ub.x, b4); b4 = fmaf(m[13], ub.y, b4);
            b4 = fmaf(m[14], ub.z, b4); b4 = fmaf(m[15], ub.w, b4);
        }
        if (k <= 5) {
            const float* m = P.ma + (k - 1) * 16;
            float vax = g_s[4 * BB + col], vbx = g_s[4 * BB + col + 1];
            float vay = g_s[3 * BB + col], vby = g_s[3 * BB + col + 1];
            float vaz = g_s[2 * BB + col], vbz = g_s[2 * BB + col + 1];
            float vaw = g_s[1 * BB + col], vbw = g_s[1 * BB + col + 1];
            a1 = fmaf(m[0],  vax, a1); a1 = fmaf(m[1],  vay, a1);
            a1 = fmaf(m[2],  vaz, a1); a1 = fmaf(m[3],  vaw, a1);
            a2 = fmaf(m[4],  vax, a2); a2 = fmaf(m[5],  vay, a2);
            a2 = fmaf(m[6],  vaz, a2); a2 = fmaf(m[7],  vaw, a2);
            a3 = fmaf(m[8],  vax, a3); a3 = fmaf(m[9],  vay, a3);
            a3 = fmaf(m[10], vaz, a3); a3 = fmaf(m[11], vaw, a3);
            a4 = fmaf(m[12], vax, a4); a4 = fmaf(m[13], vay, a4);
            a4 = fmaf(m[14], vaz, a4); a4 = fmaf(m[15], vaw, a4);
            b1 = fmaf(m[0],  vbx, b1); b1 = fmaf(m[1],  vby, b1);
            b1 = fmaf(m[2],  vbz, b1); b1 = fmaf(m[3],  vbw, b1);
            b2 = fmaf(m[4],  vbx, b2); b2 = fmaf(m[5],  vby, b2);
            b2 = fmaf(m[6],  vbz, b2); b2 = fmaf(m[7],  vbw, b2);
            b3 = fmaf(m[8],  vbx, b3); b3 = fmaf(m[9],  vby, b3);
            b3 = fmaf(m[10], vbz, b3); b3 = fmaf(m[11], vbw, b3);
            b4 = fmaf(m[12], vbx, b4); b4 = fmaf(m[13], vby, b4);
            b4 = fmaf(m[14], vbz, b4); b4 = fmaf(m[15], vbw, b4);
        }
    }

    int n0 = (k == 0) ? 5 : 64 * k;
    const float* sp = g_s + (size_t)n0 * BB + col;
    float*       op = out + (size_t)n0 * BB + col;
    if (k == 0) {
        for (int i = 0; i < 59; i++) {
            float2 sv = *(const float2*)(sp + (size_t)i * BB);
            float ta = fmaf(na4, a4, sv.x);
            ta = fmaf(na3, a3, ta);
            ta = fmaf(na2, a2, ta);
            float ya = fmaf(na1, a1, ta);
            float tb = fmaf(na4, b4, sv.y);
            tb = fmaf(na3, b3, tb);
            tb = fmaf(na2, b2, tb);
            float yb = fmaf(na1, b1, tb);
            *(float2*)(op + (size_t)i * BB) = make_float2(ya, yb);
            a4 = a3; a3 = a2; a2 = a1; a1 = ya;
            b4 = b3; b3 = b2; b2 = b1; b1 = yb;
        }
    } else {
        #pragma unroll 32
        for (int i = 0; i < 64; i++) {
            float2 sv = *(const float2*)(sp + (size_t)i * BB);
            float ta = fmaf(na4, a4, sv.x);
            ta = fmaf(na3, a3, ta);
            ta = fmaf(na2, a2, ta);
            float ya = fmaf(na1, a1, ta);
            float tb = fmaf(na4, b4, sv.y);
            tb = fmaf(na3, b3, tb);
            tb = fmaf(na2, b2, tb);
            float yb = fmaf(na1, b1, tb);
            *(float2*)(op + (size_t)i * BB) = make_float2(ya, yb);
            a4 = a3; a3 = a2; a2 = a1; a1 = ya;
            b4 = b3; b3 = b2; b2 = b1; b1 = yb;
        }
    }
}

// ---------------- host: Butterworth design (exact replica of reference, f64) ----------------
static void compute_butter(double* bc, double* ac) {
    const double PI = 3.14159265358979323846264338327950288;
    const int order = 4;
    const double wn = 25e9 / (0.5 / 1e-12);   // 0.05
    double warped = 4.0 * tan(PI * wn / 2.0);
    std::complex<double> p[4];
    for (int k = 1; k <= order; k++) {
        double ang = PI * (2.0 * k + order - 1.0) / (2.0 * order);
        p[k - 1] = warped * std::complex<double>(cos(ang), sin(ang));
    }
    double gain = warped * warped * warped * warped;
    std::complex<double> fs2(4.0, 0.0);
    std::complex<double> pz[4], prod(1.0, 0.0);
    for (int i = 0; i < 4; i++) { pz[i] = (fs2 + p[i]) / (fs2 - p[i]); prod *= (fs2 - p[i]); }
    double gz = gain * std::real(std::complex<double>(1.0, 0.0) / prod);
    const double binom[5] = {1, 4, 6, 4, 1};
    for (int i = 0; i < 5; i++) bc[i] = gz * binom[i];
    std::complex<double> c[5] = {{1,0},{0,0},{0,0},{0,0},{0,0}};
    for (int i = 0; i < 4; i++)
        for (int j = i + 1; j >= 1; j--)
            c[j] -= pz[i] * c[j - 1];
    for (int i = 0; i < 5; i++) ac[i] = std::real(c[i]);
}

// A^n (companion of the IIR state [y1,y2,y3,y4]) via column simulation, f64
static void apow(const double* ac, int n, double* A) {
    for (int c = 0; c < 4; c++) {
        double y1 = (c == 0), y2 = (c == 1), y3 = (c == 2), y4 = (c == 3);
        for (int it = 0; it < n; it++) {
            double y = -(ac[1] * y1 + ac[2] * y2 + ac[3] * y3 + ac[4] * y4);
            y4 = y3; y3 = y2; y2 = y1; y1 = y;
        }
        A[0 * 4 + c] = y1; A[1 * 4 + c] = y2; A[2 * 4 + c] = y3; A[3 * 4 + c] = y4;
    }
}

static void matmul4(const double* X, const double* Y, double* Z) {
    for (int r = 0; r < 4; r++)
        for (int c = 0; c < 4; c++) {
            double acc = 0.0;
            for (int t = 0; t < 4; t++) acc += X[r * 4 + t] * Y[t * 4 + c];
            Z[r * 4 + c] = acc;
        }
}

extern "C" void kernel_launch(void* const* d_in, const int* in_sizes, int n_in,
                              void* d_out, int out_size) {
    const float* sig   = (const float*)d_in[0];   // (16384, 512) f32
    const float* noise = (const float*)d_in[1];   // (512, 1, 16388) f32
    float* out = (float*)d_out;                   // (16384, 512) f32

    double bc[5], ac[5];
    compute_butter(bc, ac);

    static FIX fx;
    double A59[16], A64[16], Mj[16], tmp[16];
    apow(ac, 59, A59);
    apow(ac, 64, A64);
    for (int i = 0; i < 16; i++) Mj[i] = (i % 5 == 0) ? 1.0 : 0.0;   // M^0 = I
    for (int j = 0; j <= 4; j++) {
        for (int i = 0; i < 16; i++) fx.m[j * 16 + i] = (float)Mj[i];
        matmul4(Mj, A59, tmp);                   // ma[j] = M^j * A^59
        for (int i = 0; i < 16; i++) fx.ma[j * 16 + i] = (float)tmp[i];
        matmul4(Mj, A64, tmp);                   // Mj = M^{j+1}
        for (int i = 0; i < 16; i++) Mj[i] = tmp[i];
    }

    const double Qc = 1.602176563e-19, KBc = 1.3806488e-23, Tk = 300.0;
    const double BR = 5e10, DARK = 1e-10, RL = 1e6;
    double C1  = 2.0 * Qc * BR;
    double ADD = C1 * DARK + 4.0 * KBc * Tk * BR / RL;

    float na1 = (float)(-ac[1]), na2 = (float)(-ac[2]);
    float na3 = (float)(-ac[3]), na4 = (float)(-ac[4]);

    k_sd <<<(TPAD + 15) / 16, 256>>>(sig, (float)C1, (float)ADD);
    k_fir<<<dim3(16, 256), dim3(32, 8)>>>(sig, noise, out,
            (float)bc[0], (float)bc[1], (float)bc[2], (float)bc[3], (float)bc[4],
            na1, na2, na3, na4);
    k_iir<<<dim3(8, 32), dim3(32, 8)>>>(out, fx, na1, na2, na3, na4);
}

// round 10
// speedup vs baseline: 2.1129x; 1.0363x over previous
#include <cuda_runtime.h>
#include <math.h>
#include <complex>

// ---------------- problem constants ----------------
#define TT    16384          // time steps (output rows)
#define BB    512            // batch columns
#define TPAD  16388          // TT + K - 1 (K = 5)
#define NBLK  256            // IIR blocks: block k = rows 64k..64k+63 (block 0 IIR starts row 5)
#define NCG   16             // column groups of 32

// ---------------- device scratch (static, allocation-free) ----------------
__device__ float  g_sd[TPAD];           // noise std-dev per padded time step
__device__ float4 g_u[NBLK * BB];       // zero-state end states per (block,col)
__device__ float4 g_v0[BB];             // initial state v0 = [s4,s3,s2,s1] per col
__device__ int    g_flag[NCG * NBLK];   // release flags, zeroed each replay by k_sd

struct FIX {
    float m[5 * 16];      // M^j (j=0..4), M = A^64, row-major 4x4   (applied to u)
    float ma[5 * 16];     // M^i * A^59 (i=0..4)                      (applied to v0, i=k-1)
    float h[4 * 64];      // zero-input impulse tables h_c[i]
};

// ---------------- kernel 1: noise std-dev (2 rows per warp) + flag reset ----------------
__global__ __launch_bounds__(256) void k_sd(const float* __restrict__ sig,
                                            float c1, float addc) {
    // first 16 blocks also zero the flags (stream-serialized before k_fused)
    if (blockIdx.x < NCG)
        g_flag[blockIdx.x * NBLK + threadIdx.x] = 0;

    int lane = threadIdx.x & 31;
    int t0 = blockIdx.x * 16 + (threadIdx.x >> 5) * 2;
    if (t0 >= TPAD) return;
    float s0 = 0.f, s1 = 0.f;
    if (t0 >= 4) {
        const float4* r0 = (const float4*)(sig + (size_t)(t0 - 4) * BB);
        float4 a = r0[lane], b = r0[lane + 32], c = r0[lane + 64], d = r0[lane + 96];
        s0 = ((a.x + a.y) + (a.z + a.w)) + ((b.x + b.y) + (b.z + b.w))
           + ((c.x + c.y) + (c.z + c.w)) + ((d.x + d.y) + (d.z + d.w));
    }
    int t1 = t0 + 1;
    if (t1 >= 4 && t1 < TPAD) {
        const float4* r1 = (const float4*)(sig + (size_t)(t1 - 4) * BB);
        float4 a = r1[lane], b = r1[lane + 32], c = r1[lane + 64], d = r1[lane + 96];
        s1 = ((a.x + a.y) + (a.z + a.w)) + ((b.x + b.y) + (b.z + b.w))
           + ((c.x + c.y) + (c.z + c.w)) + ((d.x + d.y) + (d.z + d.w));
    }
    #pragma unroll
    for (int o = 16; o; o >>= 1) {
        s0 += __shfl_down_sync(0xffffffffu, s0, o);
        s1 += __shfl_down_sync(0xffffffffu, s1, o);
    }
    if (lane == 0) {
        g_sd[t0] = sqrtf(fmaf(c1, s0 * (1.f / 512.f), addc));
        if (t1 < TPAD) g_sd[t1] = sqrtf(fmaf(c1, s1 * (1.f / 512.f), addc));
    }
}

// ---------------- fused kernel: FIR -> zero-state scan (in smem) -> wait -> exact out ----------------
// Block (cg,k): tile = rows 64k..64k+63, cols 32cg..32cg+31.
// out[i] = y_zs[i] + sum_c h_c[i] * v_k[c];  v_k from truncated M-series over u_{k-1..k-5} (+ v0 term k<=5).
__global__ __launch_bounds__(256) void k_fused(const float* __restrict__ sig,
                                               const float* __restrict__ noise,
                                               float* __restrict__ out, FIX P,
                                               float b0, float b1, float b2, float b3, float b4,
                                               float na1, float na2, float na3, float na4) {
    __shared__ float nz[32][69];   // noise [col][j], stride 69 -> conflict-free transpose
    __shared__ float sg[68][33];   // signal [j][col]
    __shared__ float st[64][33];   // s tile -> overwritten with zero-state outputs
    __shared__ float sds[68];
    __shared__ float vv[4][33];    // reconstructed entering state per col
    int tx = threadIdx.x, ty = threadIdx.y;
    int cg = blockIdx.x, k = blockIdx.y;
    int col0 = cg * 32;
    int t0   = k * 64;

    // ---- load tiles ----
    #pragma unroll
    for (int i = 0; i < 4; i++) {
        int c = ty * 4 + i;
        const float* nrow = noise + (size_t)(col0 + c) * TPAD + t0;
        for (int j = tx; j < 68; j += 32) nz[c][j] = nrow[j];
    }
    for (int r = ty; r < 68; r += 8) {
        int trow = t0 - 4 + r;
        sg[r][tx] = (trow >= 0) ? sig[(size_t)trow * BB + col0 + tx] : 0.f;
    }
    int tid = ty * 32 + tx;
    if (tid < 68) sds[tid] = g_sd[t0 + tid];
    __syncthreads();

    // ---- FIR: 12-value window -> 8 consecutive rows per thread ----
    float xv[12];
    #pragma unroll
    for (int j = 0; j < 12; j++) {
        int jj = 8 * ty + j;
        xv[j] = fmaf(sds[jj], nz[tx][jj], sg[jj][tx]);
    }
    #pragma unroll
    for (int i = 0; i < 8; i++) {
        float acc = b0 * xv[i];
        acc = fmaf(b1, xv[i + 1], acc);
        acc = fmaf(b2, xv[i + 2], acc);
        acc = fmaf(b3, xv[i + 3], acc);
        acc = fmaf(b4, xv[i + 4], acc);
        st[8 * ty + i][tx] = acc;
    }
    __syncthreads();

    // ---- zero-state scan in place (warp 0), publish u_k (+ v0 for k==0) ----
    if (ty == 0) {
        float y1 = 0.f, y2 = 0.f, y3 = 0.f, y4 = 0.f;
        int i0 = (k == 0) ? 5 : 0;
        for (int i = i0; i < 64; i++) {
            float sv = st[i][tx];
            float t = fmaf(na4, y4, sv);
            t = fmaf(na3, y3, t);
            t = fmaf(na2, y2, t);
            float y = fmaf(na1, y1, t);
            st[i][tx] = y;
            y4 = y3; y3 = y2; y2 = y1; y1 = y;
        }
        g_u[k * BB + col0 + tx] = make_float4(y1, y2, y3, y4);
        if (k == 0)   // rows 1..4 of st untouched (scan starts at 5): still raw s
            g_v0[col0 + tx] = make_float4(st[4][tx], st[3][tx], st[2][tx], st[1][tx]);
        __threadfence();
        __syncwarp();
        if (tx == 0) atomicExch(&g_flag[cg * NBLK + k], 1);
    }
    __syncthreads();   // st now holds zero-state outputs

    // ---- reconstruct entering state v_k (warp 0) ----
    if (ty == 0) {
        if (k == 0) {
            vv[0][tx] = st[4][tx];
            vv[1][tx] = st[3][tx];
            vv[2][tx] = st[2][tx];
            vv[3][tx] = st[1][tx];
        } else {
            // spin: lane j (j<5, idx>=0) waits on producer (cg, k-1-j)
            if (tx < 5) {
                int idx = k - 1 - tx;
                if (idx >= 0) {
                    int* fp = &g_flag[cg * NBLK + idx];
                    while (atomicAdd(fp, 0) == 0) __nanosleep(32);
                }
            }
            __syncwarp();
            __threadfence();

            float v1 = 0.f, v2 = 0.f, v3 = 0.f, v4 = 0.f;
            #pragma unroll
            for (int j = 0; j <= 4; j++) {
                int idx = k - 1 - j;
                if (idx < 0) break;
                float4 u = __ldcg(&g_u[idx * BB + col0 + tx]);
                const float* m = P.m + j * 16;
                v1 = fmaf(m[0],  u.x, v1); v1 = fmaf(m[1],  u.y, v1);
                v1 = fmaf(m[2],  u.z, v1); v1 = fmaf(m[3],  u.w, v1);
                v2 = fmaf(m[4],  u.x, v2); v2 = fmaf(m[5],  u.y, v2);
                v2 = fmaf(m[6],  u.z, v2); v2 = fmaf(m[7],  u.w, v2);
                v3 = fmaf(m[8],  u.x, v3); v3 = fmaf(m[9],  u.y, v3);
                v3 = fmaf(m[10], u.z, v3); v3 = fmaf(m[11], u.w, v3);
                v4 = fmaf(m[12], u.x, v4); v4 = fmaf(m[13], u.y, v4);
                v4 = fmaf(m[14], u.z, v4); v4 = fmaf(m[15], u.w, v4);
            }
            if (k <= 5) {
                float4 u = __ldcg(&g_v0[col0 + tx]);
                const float* m = P.ma + (k - 1) * 16;
                v1 = fmaf(m[0],  u.x, v1); v1 = fmaf(m[1],  u.y, v1);
                v1 = fmaf(m[2],  u.z, v1); v1 = fmaf(m[3],  u.w, v1);
                v2 = fmaf(m[4],  u.x, v2); v2 = fmaf(m[5],  u.y, v2);
                v2 = fmaf(m[6],  u.z, v2); v2 = fmaf(m[7],  u.w, v2);
                v3 = fmaf(m[8],  u.x, v3); v3 = fmaf(m[9],  u.y, v3);
                v3 = fmaf(m[10], u.z, v3); v3 = fmaf(m[11], u.w, v3);
                v4 = fmaf(m[12], u.x, v4); v4 = fmaf(m[13], u.y, v4);
                v4 = fmaf(m[14], u.z, v4); v4 = fmaf(m[15], u.w, v4);
            }
            vv[0][tx] = v1; vv[1][tx] = v2; vv[2][tx] = v3; vv[3][tx] = v4;
        }
    }
    __syncthreads();

    // ---- epilogue: all 256 threads apply zero-input correction and write out ----
    float c1v = vv[0][tx], c2v = vv[1][tx], c3v = vv[2][tx], c4v = vv[3][tx];
    #pragma unroll
    for (int i = 0; i < 8; i++) {
        int tt = 8 * ty + i;
        float val;
        if (k == 0 && tt < 5) {
            val = st[tt][tx];                 // out rows 0..4 = s rows 0..4
        } else {
            int ii = (k == 0) ? tt - 5 : tt;  // steps since scan start (warp-uniform)
            float add = P.h[0 * 64 + ii] * c1v;
            add = fmaf(P.h[1 * 64 + ii], c2v, add);
            add = fmaf(P.h[2 * 64 + ii], c3v, add);
            add = fmaf(P.h[3 * 64 + ii], c4v, add);
            val = st[tt][tx] + add;
        }
        out[(size_t)(t0 + tt) * BB + col0 + tx] = val;
    }
}

// ---------------- host: Butterworth design (exact replica of reference, f64) ----------------
static void compute_butter(double* bc, double* ac) {
    const double PI = 3.14159265358979323846264338327950288;
    const int order = 4;
    const double wn = 25e9 / (0.5 / 1e-12);   // 0.05
    double warped = 4.0 * tan(PI * wn / 2.0);
    std::complex<double> p[4];
    for (int k = 1; k <= order; k++) {
        double ang = PI * (2.0 * k + order - 1.0) / (2.0 * order);
        p[k - 1] = warped * std::complex<double>(cos(ang), sin(ang));
    }
    double gain = warped * warped * warped * warped;
    std::complex<double> fs2(4.0, 0.0);
    std::complex<double> pz[4], prod(1.0, 0.0);
    for (int i = 0; i < 4; i++) { pz[i] = (fs2 + p[i]) / (fs2 - p[i]); prod *= (fs2 - p[i]); }
    double gz = gain * std::real(std::complex<double>(1.0, 0.0) / prod);
    const double binom[5] = {1, 4, 6, 4, 1};
    for (int i = 0; i < 5; i++) bc[i] = gz * binom[i];
    std::complex<double> c[5] = {{1,0},{0,0},{0,0},{0,0},{0,0}};
    for (int i = 0; i < 4; i++)
        for (int j = i + 1; j >= 1; j--)
            c[j] -= pz[i] * c[j - 1];
    for (int i = 0; i < 5; i++) ac[i] = std::real(c[i]);
}

// A^n (companion of the IIR state [y1,y2,y3,y4]) via column simulation, f64
static void apow(const double* ac, int n, double* A) {
    for (int c = 0; c < 4; c++) {
        double y1 = (c == 0), y2 = (c == 1), y3 = (c == 2), y4 = (c == 3);
        for (int it = 0; it < n; it++) {
            double y = -(ac[1] * y1 + ac[2] * y2 + ac[3] * y3 + ac[4] * y4);
            y4 = y3; y3 = y2; y2 = y1; y1 = y;
        }
        A[0 * 4 + c] = y1; A[1 * 4 + c] = y2; A[2 * 4 + c] = y3; A[3 * 4 + c] = y4;
    }
}

static void matmul4(const double* X, const double* Y, double* Z) {
    for (int r = 0; r < 4; r++)
        for (int c = 0; c < 4; c++) {
            double acc = 0.0;
            for (int t = 0; t < 4; t++) acc += X[r * 4 + t] * Y[t * 4 + c];
            Z[r * 4 + c] = acc;
        }
}

extern "C" void kernel_launch(void* const* d_in, const int* in_sizes, int n_in,
                              void* d_out, int out_size) {
    const float* sig   = (const float*)d_in[0];   // (16384, 512) f32
    const float* noise = (const float*)d_in[1];   // (512, 1, 16388) f32
    float* out = (float*)d_out;                   // (16384, 512) f32

    double bc[5], ac[5];
    compute_butter(bc, ac);

    static FIX fx;
    // zero-input impulse tables h_c[i] (response i steps after start, unit state e_c)
    for (int c = 0; c < 4; c++) {
        double y1 = (c == 0), y2 = (c == 1), y3 = (c == 2), y4 = (c == 3);
        for (int i = 0; i < 64; i++) {
            double y = -(ac[1] * y1 + ac[2] * y2 + ac[3] * y3 + ac[4] * y4);
            fx.h[c * 64 + i] = (float)y;
            y4 = y3; y3 = y2; y2 = y1; y1 = y;
        }
    }
    double A59[16], A64[16], Mj[16], tmp[16];
    apow(ac, 59, A59);
    apow(ac, 64, A64);
    for (int i = 0; i < 16; i++) Mj[i] = (i % 5 == 0) ? 1.0 : 0.0;   // M^0 = I
    for (int j = 0; j <= 4; j++) {
        for (int i = 0; i < 16; i++) fx.m[j * 16 + i] = (float)Mj[i];
        matmul4(Mj, A59, tmp);                   // ma[j] = M^j * A^59
        for (int i = 0; i < 16; i++) fx.ma[j * 16 + i] = (float)tmp[i];
        matmul4(Mj, A64, tmp);                   // Mj = M^{j+1}
        for (int i = 0; i < 16; i++) Mj[i] = tmp[i];
    }

    const double Qc = 1.602176563e-19, KBc = 1.3806488e-23, Tk = 300.0;
    const double BR = 5e10, DARK = 1e-10, RL = 1e6;
    double C1  = 2.0 * Qc * BR;
    double ADD = C1 * DARK + 4.0 * KBc * Tk * BR / RL;

    float na1 = (float)(-ac[1]), na2 = (float)(-ac[2]);
    float na3 = (float)(-ac[3]), na4 = (float)(-ac[4]);

    k_sd   <<<(TPAD + 15) / 16, 256>>>(sig, (float)C1, (float)ADD);
    k_fused<<<dim3(NCG, NBLK), dim3(32, 8)>>>(sig, noise, out, fx,
              (float)bc[0], (float)bc[1], (float)bc[2], (float)bc[3], (float)bc[4],
              na1, na2, na3, na4);
}

// round 11
// speedup vs baseline: 2.6200x; 1.2400x over previous
#include <cuda_runtime.h>
#include <math.h>
#include <complex>

// ---------------- problem constants ----------------
#define TT    16384          // time steps (output rows)
#define BB    512            // batch columns
#define TPAD  16388          // TT + K - 1 (K = 5)
#define NBLK  256            // IIR blocks: block k = rows 64k..64k+63 (block 0 IIR starts row 5)
#define NCG   16             // column groups of 32

// ---------------- device scratch (static, allocation-free) ----------------
__device__ float  g_sd[TPAD];           // noise std-dev per padded time step
__device__ float4 g_u[NBLK * BB];       // zero-state end states per (block,col)
__device__ float4 g_v0[BB];             // initial state v0 = [s4,s3,s2,s1] per col
__device__ int    g_flag[NCG * NBLK];   // release flags, zeroed each replay by k_sd

struct FIX {
    float m[5 * 16];      // M^j (j=0..4), M = A^64, row-major 4x4   (applied to u)
    float ma[5 * 16];     // M^i * A^59 (i=0..4)                      (applied to v0, i=k-1)
    float h[4 * 64];      // zero-input impulse tables h_c[i]
};

// ---------------- kernel 1: noise std-dev (2 rows per warp) + flag reset ----------------
__global__ __launch_bounds__(256) void k_sd(const float* __restrict__ sig,
                                            float c1, float addc) {
    if (blockIdx.x < NCG)
        g_flag[blockIdx.x * NBLK + threadIdx.x] = 0;

    int lane = threadIdx.x & 31;
    int t0 = blockIdx.x * 16 + (threadIdx.x >> 5) * 2;
    if (t0 >= TPAD) return;
    float s0 = 0.f, s1 = 0.f;
    if (t0 >= 4) {
        const float4* r0 = (const float4*)(sig + (size_t)(t0 - 4) * BB);
        float4 a = r0[lane], b = r0[lane + 32], c = r0[lane + 64], d = r0[lane + 96];
        s0 = ((a.x + a.y) + (a.z + a.w)) + ((b.x + b.y) + (b.z + b.w))
           + ((c.x + c.y) + (c.z + c.w)) + ((d.x + d.y) + (d.z + d.w));
    }
    int t1 = t0 + 1;
    if (t1 >= 4 && t1 < TPAD) {
        const float4* r1 = (const float4*)(sig + (size_t)(t1 - 4) * BB);
        float4 a = r1[lane], b = r1[lane + 32], c = r1[lane + 64], d = r1[lane + 96];
        s1 = ((a.x + a.y) + (a.z + a.w)) + ((b.x + b.y) + (b.z + b.w))
           + ((c.x + c.y) + (c.z + c.w)) + ((d.x + d.y) + (d.z + d.w));
    }
    #pragma unroll
    for (int o = 16; o; o >>= 1) {
        s0 += __shfl_down_sync(0xffffffffu, s0, o);
        s1 += __shfl_down_sync(0xffffffffu, s1, o);
    }
    if (lane == 0) {
        g_sd[t0] = sqrtf(fmaf(c1, s0 * (1.f / 512.f), addc));
        if (t1 < TPAD) g_sd[t1] = sqrtf(fmaf(c1, s1 * (1.f / 512.f), addc));
    }
}

// ---------------- fused kernel: FIR -> {scan (w0) || state-reconstruct (w1)} -> exact out ----------------
__global__ __launch_bounds__(256) void k_fused(const float* __restrict__ sig,
                                               const float* __restrict__ noise,
                                               float* __restrict__ out, FIX P,
                                               float b0, float b1, float b2, float b3, float b4,
                                               float na1, float na2, float na3, float na4) {
    __shared__ float nz[32][69];   // noise [col][j], stride 69 -> conflict-free transpose
    __shared__ float sg[68][33];   // signal [j][col]
    __shared__ float st[64][33];   // s tile -> overwritten with zero-state outputs
    __shared__ float sds[68];
    __shared__ float vv[4][33];    // reconstructed entering state per col
    int tx = threadIdx.x, ty = threadIdx.y;
    int cg = blockIdx.x, k = blockIdx.y;
    int col0 = cg * 32;
    int t0   = k * 64;

    // ---- load tiles (fixed-trip, unrolled) ----
    #pragma unroll
    for (int i = 0; i < 4; i++) {
        int c = ty * 4 + i;
        const float* nrow = noise + (size_t)(col0 + c) * TPAD + t0;
        nz[c][tx]      = nrow[tx];
        nz[c][tx + 32] = nrow[tx + 32];
        if (tx < 4) nz[c][tx + 64] = nrow[tx + 64];
    }
    #pragma unroll
    for (int j = 0; j < 9; j++) {
        int r = ty + 8 * j;
        if (r < 68) {
            int trow = t0 - 4 + r;
            sg[r][tx] = (trow >= 0) ? sig[(size_t)trow * BB + col0 + tx] : 0.f;
        }
    }
    int tid = ty * 32 + tx;
    if (tid < 68) sds[tid] = g_sd[t0 + tid];
    __syncthreads();

    // ---- FIR: 12-value window -> 8 consecutive rows per thread ----
    float xv[12];
    #pragma unroll
    for (int j = 0; j < 12; j++) {
        int jj = 8 * ty + j;
        xv[j] = fmaf(sds[jj], nz[tx][jj], sg[jj][tx]);
    }
    #pragma unroll
    for (int i = 0; i < 8; i++) {
        float acc = b0 * xv[i];
        acc = fmaf(b1, xv[i + 1], acc);
        acc = fmaf(b2, xv[i + 2], acc);
        acc = fmaf(b3, xv[i + 3], acc);
        acc = fmaf(b4, xv[i + 4], acc);
        st[8 * ty + i][tx] = acc;
    }
    __syncthreads();

    bool kz = (k == 0);
    if (ty == 0) {
        // ---- zero-state scan, unrollable: k==0 handled by zeroed inputs (state stays 0) ----
        float p1 = st[1][tx], p2 = st[2][tx], p3 = st[3][tx], p4 = st[4][tx];
        float y1 = 0.f, y2 = 0.f, y3 = 0.f, y4 = 0.f;
        #pragma unroll 16
        for (int i = 0; i < 64; i++) {
            float sv = st[i][tx];
            bool skip = kz && (i < 5);          // only first unrolled chunk carries this
            if (skip) sv = 0.f;
            float t = fmaf(na4, y4, sv);
            t = fmaf(na3, y3, t);
            t = fmaf(na2, y2, t);
            float y = fmaf(na1, y1, t);
            if (!skip) st[i][tx] = y;           // keep raw s rows 0..4 for k==0
            y4 = y3; y3 = y2; y2 = y1; y1 = y;
        }
        g_u[k * BB + col0 + tx] = make_float4(y1, y2, y3, y4);
        if (kz)
            g_v0[col0 + tx] = make_float4(p4, p3, p2, p1);
        __threadfence();
        __syncwarp();
        if (tx == 0) atomicExch(&g_flag[cg * NBLK + k], 1);
    } else if (ty == 1) {
        // ---- concurrent: reconstruct entering state v_k from predecessors ----
        if (kz) {
            vv[0][tx] = st[4][tx];    // rows 1..4 stay raw during warp0's scan (it skips them)
            vv[1][tx] = st[3][tx];
            vv[2][tx] = st[2][tx];
            vv[3][tx] = st[1][tx];
        } else {
            if (tx < 5) {
                int idx = k - 1 - tx;
                if (idx >= 0) {
                    volatile int* fp = (volatile int*)&g_flag[cg * NBLK + idx];
                    while (*fp == 0) __nanosleep(32);
                }
            }
            __syncwarp();
            __threadfence();

            float v1 = 0.f, v2 = 0.f, v3 = 0.f, v4 = 0.f;
            #pragma unroll
            for (int j = 0; j <= 4; j++) {
                int idx = k - 1 - j;
                if (idx < 0) break;
                float4 u = __ldcg(&g_u[idx * BB + col0 + tx]);
                const float* m = P.m + j * 16;
                v1 = fmaf(m[0],  u.x, v1); v1 = fmaf(m[1],  u.y, v1);
                v1 = fmaf(m[2],  u.z, v1); v1 = fmaf(m[3],  u.w, v1);
                v2 = fmaf(m[4],  u.x, v2); v2 = fmaf(m[5],  u.y, v2);
                v2 = fmaf(m[6],  u.z, v2); v2 = fmaf(m[7],  u.w, v2);
                v3 = fmaf(m[8],  u.x, v3); v3 = fmaf(m[9],  u.y, v3);
                v3 = fmaf(m[10], u.z, v3); v3 = fmaf(m[11], u.w, v3);
                v4 = fmaf(m[12], u.x, v4); v4 = fmaf(m[13], u.y, v4);
                v4 = fmaf(m[14], u.z, v4); v4 = fmaf(m[15], u.w, v4);
            }
            if (k <= 5) {
                float4 u = __ldcg(&g_v0[col0 + tx]);
                const float* m = P.ma + (k - 1) * 16;
                v1 = fmaf(m[0],  u.x, v1); v1 = fmaf(m[1],  u.y, v1);
                v1 = fmaf(m[2],  u.z, v1); v1 = fmaf(m[3],  u.w, v1);
                v2 = fmaf(m[4],  u.x, v2); v2 = fmaf(m[5],  u.y, v2);
                v2 = fmaf(m[6],  u.z, v2); v2 = fmaf(m[7],  u.w, v2);
                v3 = fmaf(m[8],  u.x, v3); v3 = fmaf(m[9],  u.y, v3);
                v3 = fmaf(m[10], u.z, v3); v3 = fmaf(m[11], u.w, v3);
                v4 = fmaf(m[12], u.x, v4); v4 = fmaf(m[13], u.y, v4);
                v4 = fmaf(m[14], u.z, v4); v4 = fmaf(m[15], u.w, v4);
            }
            vv[0][tx] = v1; vv[1][tx] = v2; vv[2][tx] = v3; vv[3][tx] = v4;
        }
    }
    __syncthreads();   // st = zero-state outputs; vv = entering state

    // ---- epilogue: all 256 threads apply zero-input correction and write out ----
    float c1v = vv[0][tx], c2v = vv[1][tx], c3v = vv[2][tx], c4v = vv[3][tx];
    #pragma unroll
    for (int i = 0; i < 8; i++) {
        int tt = 8 * ty + i;
        float val;
        if (kz && tt < 5) {
            val = st[tt][tx];                 // out rows 0..4 = s rows 0..4
        } else {
            int ii = kz ? tt - 5 : tt;        // steps since scan start (warp-uniform)
            float add = P.h[0 * 64 + ii] * c1v;
            add = fmaf(P.h[1 * 64 + ii], c2v, add);
            add = fmaf(P.h[2 * 64 + ii], c3v, add);
            add = fmaf(P.h[3 * 64 + ii], c4v, add);
            val = st[tt][tx] + add;
        }
        out[(size_t)(t0 + tt) * BB + col0 + tx] = val;
    }
}

// ---------------- host: Butterworth design (exact replica of reference, f64) ----------------
static void compute_butter(double* bc, double* ac) {
    const double PI = 3.14159265358979323846264338327950288;
    const int order = 4;
    const double wn = 25e9 / (0.5 / 1e-12);   // 0.05
    double warped = 4.0 * tan(PI * wn / 2.0);
    std::complex<double> p[4];
    for (int k = 1; k <= order; k++) {
        double ang = PI * (2.0 * k + order - 1.0) / (2.0 * order);
        p[k - 1] = warped * std::complex<double>(cos(ang), sin(ang));
    }
    double gain = warped * warped * warped * warped;
    std::complex<double> fs2(4.0, 0.0);
    std::complex<double> pz[4], prod(1.0, 0.0);
    for (int i = 0; i < 4; i++) { pz[i] = (fs2 + p[i]) / (fs2 - p[i]); prod *= (fs2 - p[i]); }
    double gz = gain * std::real(std::complex<double>(1.0, 0.0) / prod);
    const double binom[5] = {1, 4, 6, 4, 1};
    for (int i = 0; i < 5; i++) bc[i] = gz * binom[i];
    std::complex<double> c[5] = {{1,0},{0,0},{0,0},{0,0},{0,0}};
    for (int i = 0; i < 4; i++)
        for (int j = i + 1; j >= 1; j--)
            c[j] -= pz[i] * c[j - 1];
    for (int i = 0; i < 5; i++) ac[i] = std::real(c[i]);
}

// A^n (companion of the IIR state [y1,y2,y3,y4]) via column simulation, f64
static void apow(const double* ac, int n, double* A) {
    for (int c = 0; c < 4; c++) {
        double y1 = (c == 0), y2 = (c == 1), y3 = (c == 2), y4 = (c == 3);
        for (int it = 0; it < n; it++) {
            double y = -(ac[1] * y1 + ac[2] * y2 + ac[3] * y3 + ac[4] * y4);
            y4 = y3; y3 = y2; y2 = y1; y1 = y;
        }
        A[0 * 4 + c] = y1; A[1 * 4 + c] = y2; A[2 * 4 + c] = y3; A[3 * 4 + c] = y4;
    }
}

static void matmul4(const double* X, const double* Y, double* Z) {
    for (int r = 0; r < 4; r++)
        for (int c = 0; c < 4; c++) {
            double acc = 0.0;
            for (int t = 0; t < 4; t++) acc += X[r * 4 + t] * Y[t * 4 + c];
            Z[r * 4 + c] = acc;
        }
}

extern "C" void kernel_launch(void* const* d_in, const int* in_sizes, int n_in,
                              void* d_out, int out_size) {
    const float* sig   = (const float*)d_in[0];   // (16384, 512) f32
    const float* noise = (const float*)d_in[1];   // (512, 1, 16388) f32
    float* out = (float*)d_out;                   // (16384, 512) f32

    double bc[5], ac[5];
    compute_butter(bc, ac);

    static FIX fx;
    for (int c = 0; c < 4; c++) {
        double y1 = (c == 0), y2 = (c == 1), y3 = (c == 2), y4 = (c == 3);
        for (int i = 0; i < 64; i++) {
            double y = -(ac[1] * y1 + ac[2] * y2 + ac[3] * y3 + ac[4] * y4);
            fx.h[c * 64 + i] = (float)y;
            y4 = y3; y3 = y2; y2 = y1; y1 = y;
        }
    }
    double A59[16], A64[16], Mj[16], tmp[16];
    apow(ac, 59, A59);
    apow(ac, 64, A64);
    for (int i = 0; i < 16; i++) Mj[i] = (i % 5 == 0) ? 1.0 : 0.0;   // M^0 = I
    for (int j = 0; j <= 4; j++) {
        for (int i = 0; i < 16; i++) fx.m[j * 16 + i] = (float)Mj[i];
        matmul4(Mj, A59, tmp);                   // ma[j] = M^j * A^59
        for (int i = 0; i < 16; i++) fx.ma[j * 16 + i] = (float)tmp[i];
        matmul4(Mj, A64, tmp);                   // Mj = M^{j+1}
        for (int i = 0; i < 16; i++) Mj[i] = tmp[i];
    }

    const double Qc = 1.602176563e-19, KBc = 1.3806488e-23, Tk = 300.0;
    const double BR = 5e10, DARK = 1e-10, RL = 1e6;
    double C1  = 2.0 * Qc * BR;
    double ADD = C1 * DARK + 4.0 * KBc * Tk * BR / RL;

    float na1 = (float)(-ac[1]), na2 = (float)(-ac[2]);
    float na3 = (float)(-ac[3]), na4 = (float)(-ac[4]);

    k_sd   <<<(TPAD + 15) / 16, 256>>>(sig, (float)C1, (float)ADD);
    k_fused<<<dim3(NCG, NBLK), dim3(32, 8)>>>(sig, noise, out, fx,
              (float)bc[0], (float)bc[1], (float)bc[2], (float)bc[3], (float)bc[4],
              na1, na2, na3, na4);
}

// round 13
// speedup vs baseline: 2.9709x; 1.1339x over previous
#include <cuda_runtime.h>
#include <math.h>
#include <complex>

// ---------------- problem constants ----------------
#define TT    16384          // time steps (output rows)
#define BB    512            // batch columns
#define TPAD  16388          // TT + K - 1 (K = 5)
#define NBLK  256            // IIR blocks: block k = rows 64k..64k+63 (block 0 IIR starts row 5)
#define NCG   16             // column groups of 32

// ---------------- device scratch (static, allocation-free) ----------------
__device__ float  g_sd[TPAD];           // noise std-dev per padded time step
__device__ float4 g_u[NBLK * BB];       // zero-state end states per (block,col)
__device__ float4 g_v0[BB];             // initial state v0 = [s4,s3,s2,s1] per col
__device__ int    g_flag[NCG * NBLK];   // release flags, zeroed each replay by k_sd

struct FIX {
    float m[5 * 16];      // M^j (j=0..4), M = A^64, row-major 4x4   (applied to u)
    float ma[5 * 16];     // M^i * A^59 (i=0..4)                      (applied to v0, i=k-1)
    float hf[4 * 64];     // zero-input impulse tables hf_c[i], 64 steps (f64-built)
};

// ---------------- kernel 1: noise std-dev (2 rows per warp) + flag reset ----------------
__global__ __launch_bounds__(256) void k_sd(const float* __restrict__ sig,
                                            float c1, float addc) {
    if (blockIdx.x < NCG)
        g_flag[blockIdx.x * NBLK + threadIdx.x] = 0;

    int lane = threadIdx.x & 31;
    int t0 = blockIdx.x * 16 + (threadIdx.x >> 5) * 2;
    if (t0 >= TPAD) return;
    float s0 = 0.f, s1 = 0.f;
    if (t0 >= 4) {
        const float4* r0 = (const float4*)(sig + (size_t)(t0 - 4) * BB);
        float4 a = r0[lane], b = r0[lane + 32], c = r0[lane + 64], d = r0[lane + 96];
        s0 = ((a.x + a.y) + (a.z + a.w)) + ((b.x + b.y) + (b.z + b.w))
           + ((c.x + c.y) + (c.z + c.w)) + ((d.x + d.y) + (d.z + d.w));
    }
    int t1 = t0 + 1;
    if (t1 >= 4 && t1 < TPAD) {
        const float4* r1 = (const float4*)(sig + (size_t)(t1 - 4) * BB);
        float4 a = r1[lane], b = r1[lane + 32], c = r1[lane + 64], d = r1[lane + 96];
        s1 = ((a.x + a.y) + (a.z + a.w)) + ((b.x + b.y) + (b.z + b.w))
           + ((c.x + c.y) + (c.z + c.w)) + ((d.x + d.y) + (d.z + d.w));
    }
    #pragma unroll
    for (int o = 16; o; o >>= 1) {
        s0 += __shfl_down_sync(0xffffffffu, s0, o);
        s1 += __shfl_down_sync(0xffffffffu, s1, o);
    }
    if (lane == 0) {
        g_sd[t0] = sqrtf(fmaf(c1, s0 * (1.f / 512.f), addc));
        if (t1 < TPAD) g_sd[t1] = sqrtf(fmaf(c1, s1 * (1.f / 512.f), addc));
    }
}

// 4x4 matvec helper (row-major m), accumulate into (r1..r4)
#define MV4(m, x1, x2, x3, x4, r1, r2, r3, r4)                        \
    do {                                                              \
        r1 = fmaf((m)[0],  x1, r1); r1 = fmaf((m)[1],  x2, r1);       \
        r1 = fmaf((m)[2],  x3, r1); r1 = fmaf((m)[3],  x4, r1);       \
        r2 = fmaf((m)[4],  x1, r2); r2 = fmaf((m)[5],  x2, r2);       \
        r2 = fmaf((m)[6],  x3, r2); r2 = fmaf((m)[7],  x4, r2);       \
        r3 = fmaf((m)[8],  x1, r3); r3 = fmaf((m)[9],  x2, r3);       \
        r3 = fmaf((m)[10], x3, r3); r3 = fmaf((m)[11], x4, r3);       \
        r4 = fmaf((m)[12], x1, r4); r4 = fmaf((m)[13], x2, r4);       \
        r4 = fmaf((m)[14], x3, r4); r4 = fmaf((m)[15], x4, r4);       \
    } while (0)

// zero-input dot: sum_c hf_c[i] * v_c
#define HDOT(P, i, v1, v2, v3, v4)                                     \
    ( fmaf((P).hf[3 * 64 + (i)], v4,                                   \
      fmaf((P).hf[2 * 64 + (i)], v3,                                   \
      fmaf((P).hf[1 * 64 + (i)], v2, (P).hf[0 * 64 + (i)] * v1))) )

// ---------------- fused kernel: FIR -> {half-scans (w0,w1) || reconstruct (w2)} -> exact out ----
__global__ __launch_bounds__(256) void k_fused(const float* __restrict__ sig,
                                               const float* __restrict__ noise,
                                               float* __restrict__ out, FIX P,
                                               float b0, float b1, float b2, float b3, float b4,
                                               float na1, float na2, float na3, float na4) {
    __shared__ float nz[32][69];   // noise [col][j], stride 69 -> conflict-free transpose
    __shared__ float sg[68][33];   // signal [j][col]
    __shared__ float st[64][33];   // s tile -> overwritten with half-local zero-state outputs
    __shared__ float sds[68];
    __shared__ float vv[4][33];    // reconstructed entering state per col
    __shared__ float sua[4][33];   // first-half zero-state end state per col
    int tx = threadIdx.x, ty = threadIdx.y;
    int cg = blockIdx.x, k = blockIdx.y;
    int col0 = cg * 32;
    int t0   = k * 64;

    // ---- load tiles (fixed-trip, unrolled) ----
    #pragma unroll
    for (int i = 0; i < 4; i++) {
        int c = ty * 4 + i;
        const float* nrow = noise + (size_t)(col0 + c) * TPAD + t0;
        nz[c][tx]      = nrow[tx];
        nz[c][tx + 32] = nrow[tx + 32];
        if (tx < 4) nz[c][tx + 64] = nrow[tx + 64];
    }
    #pragma unroll
    for (int j = 0; j < 9; j++) {
        int r = ty + 8 * j;
        if (r < 68) {
            int trow = t0 - 4 + r;
            sg[r][tx] = (trow >= 0) ? sig[(size_t)trow * BB + col0 + tx] : 0.f;
        }
    }
    int tid = ty * 32 + tx;
    if (tid < 68) sds[tid] = g_sd[t0 + tid];
    __syncthreads();

    // ---- FIR: 12-value window -> 8 consecutive rows per thread ----
    float xv[12];
    #pragma unroll
    for (int j = 0; j < 12; j++) {
        int jj = 8 * ty + j;
        xv[j] = fmaf(sds[jj], nz[tx][jj], sg[jj][tx]);
    }
    #pragma unroll
    for (int i = 0; i < 8; i++) {
        float acc = b0 * xv[i];
        acc = fmaf(b1, xv[i + 1], acc);
        acc = fmaf(b2, xv[i + 2], acc);
        acc = fmaf(b3, xv[i + 3], acc);
        acc = fmaf(b4, xv[i + 4], acc);
        st[8 * ty + i][tx] = acc;
    }
    __syncthreads();

    bool kz = (k == 0);
    if (ty == 0) {
        // ---- first-half zero-state scan (rows 0..31); k==0: rows 0..4 zeroed, stores skipped ----
        float p1 = st[1][tx], p2 = st[2][tx], p3 = st[3][tx], p4 = st[4][tx];
        float y1 = 0.f, y2 = 0.f, y3 = 0.f, y4 = 0.f;
        #pragma unroll
        for (int i = 0; i < 32; i++) {
            float sv = st[i][tx];
            bool skip = kz && (i < 5);
            if (skip) sv = 0.f;
            float t = fmaf(na4, y4, sv);
            t = fmaf(na3, y3, t);
            t = fmaf(na2, y2, t);
            float y = fmaf(na1, y1, t);
            if (!skip) st[i][tx] = y;
            y4 = y3; y3 = y2; y2 = y1; y1 = y;
        }
        sua[0][tx] = y1; sua[1][tx] = y2; sua[2][tx] = y3; sua[3][tx] = y4;
        if (kz)
            g_v0[col0 + tx] = make_float4(p4, p3, p2, p1);
        asm volatile("bar.sync 1, 64;" ::: "memory");
    } else if (ty == 1) {
        // ---- second-half zero-state scan (rows 32..63), state local to row 32 ----
        float y1 = 0.f, y2 = 0.f, y3 = 0.f, y4 = 0.f;
        #pragma unroll
        for (int i = 32; i < 64; i++) {
            float sv = st[i][tx];
            float t = fmaf(na4, y4, sv);
            t = fmaf(na3, y3, t);
            t = fmaf(na2, y2, t);
            float y = fmaf(na1, y1, t);
            st[i][tx] = y;
            y4 = y3; y3 = y2; y2 = y1; y1 = y;
        }
        asm volatile("bar.sync 1, 64;" ::: "memory");
        // ---- combine via impulse tables (no matrix cascade):
        // full-block zs end state u_c = zs2_end_c + zi(ua) at rows 63..60
        float a1 = sua[0][tx], a2 = sua[1][tx], a3 = sua[2][tx], a4 = sua[3][tx];
        float u1 = y1 + HDOT(P, 31, a1, a2, a3, a4);   // row 63: 31 steps past row-32 state
        float u2 = y2 + HDOT(P, 30, a1, a2, a3, a4);
        float u3 = y3 + HDOT(P, 29, a1, a2, a3, a4);
        float u4 = y4 + HDOT(P, 28, a1, a2, a3, a4);
        g_u[k * BB + col0 + tx] = make_float4(u1, u2, u3, u4);
        __threadfence();
        __syncwarp();
        if (tx == 0) atomicExch(&g_flag[cg * NBLK + k], 1);
    } else if (ty == 2) {
        // ---- concurrent: reconstruct entering state v_k from predecessors ----
        if (kz) {
            vv[0][tx] = st[4][tx];    // rows 1..4 stay raw (warp0 skips their stores)
            vv[1][tx] = st[3][tx];
            vv[2][tx] = st[2][tx];
            vv[3][tx] = st[1][tx];
        } else {
            if (tx < 5) {
                int idx = k - 1 - tx;
                if (idx >= 0) {
                    volatile int* fp = (volatile int*)&g_flag[cg * NBLK + idx];
                    while (*fp == 0) __nanosleep(32);
                }
            }
            __syncwarp();
            __threadfence();

            float v1 = 0.f, v2 = 0.f, v3 = 0.f, v4 = 0.f;
            #pragma unroll
            for (int j = 0; j <= 4; j++) {
                int idx = k - 1 - j;
                if (idx < 0) break;
                float4 u = __ldcg(&g_u[idx * BB + col0 + tx]);
                const float* m = P.m + j * 16;
                MV4(m, u.x, u.y, u.z, u.w, v1, v2, v3, v4);
            }
            if (k <= 5) {
                float4 u = __ldcg(&g_v0[col0 + tx]);
                const float* m = P.ma + (k - 1) * 16;
                MV4(m, u.x, u.y, u.z, u.w, v1, v2, v3, v4);
            }
            vv[0][tx] = v1; vv[1][tx] = v2; vv[2][tx] = v3; vv[3][tx] = v4;
        }
    }
    __syncthreads();   // st = half-local zs outputs; vv = entering state; sua = half state

    // ---- epilogue: corrections via f64-built impulse tables only ----
    float v1 = vv[0][tx], v2 = vv[1][tx], v3 = vv[2][tx], v4 = vv[3][tx];
    float a1 = 0.f, a2 = 0.f, a3 = 0.f, a4 = 0.f;
    if (ty >= 4) {   // second half also corrects with ua
        a1 = sua[0][tx]; a2 = sua[1][tx]; a3 = sua[2][tx]; a4 = sua[3][tx];
    }
    #pragma unroll
    for (int i = 0; i < 8; i++) {
        int tt = 8 * ty + i;
        float val;
        if (kz && tt < 5) {
            val = st[tt][tx];                 // out rows 0..4 = s rows 0..4
        } else {
            int ii = kz ? tt - 5 : tt;        // steps since block start (warp-uniform)
            float add = HDOT(P, ii, v1, v2, v3, v4);
            if (ty >= 4)                      // + zi of first-half state, tt-32 steps past row 32
                add += HDOT(P, tt - 32, a1, a2, a3, a4);
            val = st[tt][tx] + add;
        }
        out[(size_t)(t0 + tt) * BB + col0 + tx] = val;
    }
}

// ---------------- host: Butterworth design (exact replica of reference, f64) ----------------
static void compute_butter(double* bc, double* ac) {
    const double PI = 3.14159265358979323846264338327950288;
    const int order = 4;
    const double wn = 25e9 / (0.5 / 1e-12);   // 0.05
    double warped = 4.0 * tan(PI * wn / 2.0);
    std::complex<double> p[4];
    for (int k = 1; k <= order; k++) {
        double ang = PI * (2.0 * k + order - 1.0) / (2.0 * order);
        p[k - 1] = warped * std::complex<double>(cos(ang), sin(ang));
    }
    double gain = warped * warped * warped * warped;
    std::complex<double> fs2(4.0, 0.0);
    std::complex<double> pz[4], prod(1.0, 0.0);
    for (int i = 0; i < 4; i++) { pz[i] = (fs2 + p[i]) / (fs2 - p[i]); prod *= (fs2 - p[i]); }
    double gz = gain * std::real(std::complex<double>(1.0, 0.0) / prod);
    const double binom[5] = {1, 4, 6, 4, 1};
    for (int i = 0; i < 5; i++) bc[i] = gz * binom[i];
    std::complex<double> c[5] = {{1,0},{0,0},{0,0},{0,0},{0,0}};
    for (int i = 0; i < 4; i++)
        for (int j = i + 1; j >= 1; j--)
            c[j] -= pz[i] * c[j - 1];
    for (int i = 0; i < 5; i++) ac[i] = std::real(c[i]);
}

// A^n (companion of the IIR state [y1,y2,y3,y4]) via column simulation, f64
static void apow(const double* ac, int n, double* A) {
    for (int c = 0; c < 4; c++) {
        double y1 = (c == 0), y2 = (c == 1), y3 = (c == 2), y4 = (c == 3);
        for (int it = 0; it < n; it++) {
            double y = -(ac[1] * y1 + ac[2] * y2 + ac[3] * y3 + ac[4] * y4);
            y4 = y3; y3 = y2; y2 = y1; y1 = y;
        }
        A[0 * 4 + c] = y1; A[1 * 4 + c] = y2; A[2 * 4 + c] = y3; A[3 * 4 + c] = y4;
    }
}

static void matmul4(const double* X, const double* Y, double* Z) {
    for (int r = 0; r < 4; r++)
        for (int c = 0; c < 4; c++) {
            double acc = 0.0;
            for (int t = 0; t < 4; t++) acc += X[r * 4 + t] * Y[t * 4 + c];
            Z[r * 4 + c] = acc;
        }
}

extern "C" void kernel_launch(void* const* d_in, const int* in_sizes, int n_in,
                              void* d_out, int out_size) {
    const float* sig   = (const float*)d_in[0];   // (16384, 512) f32
    const float* noise = (const float*)d_in[1];   // (512, 1, 16388) f32
    float* out = (float*)d_out;                   // (16384, 512) f32

    double bc[5], ac[5];
    compute_butter(bc, ac);

    static FIX fx;
    // zero-input impulse tables hf_c[i], 64 steps (f64)
    for (int c = 0; c < 4; c++) {
        double y1 = (c == 0), y2 = (c == 1), y3 = (c == 2), y4 = (c == 3);
        for (int i = 0; i < 64; i++) {
            double y = -(ac[1] * y1 + ac[2] * y2 + ac[3] * y3 + ac[4] * y4);
            fx.hf[c * 64 + i] = (float)y;
            y4 = y3; y3 = y2; y2 = y1; y1 = y;
        }
    }
    double A59[16], A64[16], Mj[16], tmp[16];
    apow(ac, 59, A59);
    apow(ac, 64, A64);
    for (int i = 0; i < 16; i++) Mj[i] = (i % 5 == 0) ? 1.0 : 0.0;   // M^0 = I
    for (int j = 0; j <= 4; j++) {
        for (int i = 0; i < 16; i++) fx.m[j * 16 + i] = (float)Mj[i];
        matmul4(Mj, A59, tmp);                   // ma[j] = M^j * A^59
        for (int i = 0; i < 16; i++) fx.ma[j * 16 + i] = (float)tmp[i];
        matmul4(Mj, A64, tmp);                   // Mj = M^{j+1}
        for (int i = 0; i < 16; i++) Mj[i] = tmp[i];
    }

    const double Qc = 1.602176563e-19, KBc = 1.3806488e-23, Tk = 300.0;
    const double BR = 5e10, DARK = 1e-10, RL = 1e6;
    double C1  = 2.0 * Qc * BR;
    double ADD = C1 * DARK + 4.0 * KBc * Tk * BR / RL;

    float na1 = (float)(-ac[1]), na2 = (float)(-ac[2]);
    float na3 = (float)(-ac[3]), na4 = (float)(-ac[4]);

    k_sd   <<<(TPAD + 15) / 16, 256>>>(sig, (float)C1, (float)ADD);
    k_fused<<<dim3(NCG, NBLK), dim3(32, 8)>>>(sig, noise, out, fx,
              (float)bc[0], (float)bc[1], (float)bc[2], (float)bc[3], (float)bc[4],
              na1, na2, na3, na4);
}